// round 3
// baseline (speedup 1.0000x reference)
#include <cuda_runtime.h>

// Problem constants (fixed by reference setup)
#define BSZ     2
#define SEQ     4096
#define HQN     32
#define HKV     2
#define DIM     128
#define STRIDEW 16
#define BLKW    32
#define NBL     255
#define GRP     16
#define SCALE   0.08838834764831845f   // 1/sqrt(128)

#define OUT_ELEMS  ((size_t)BSZ*SEQ*HQN*DIM)            // 33,554,432
#define ATTN_ELEMS ((size_t)BSZ*HQN*SEQ*NBL)            // 66,846,720

// Scratch for compressed K/V: (BS, NB, HKV, D)
__device__ float g_kc[BSZ*NBL*HKV*DIM];
__device__ float g_vc[BSZ*NBL*HKV*DIM];

// ---------------------------------------------------------------------------
// Compression kernel.
// grid (16 nb-groups, 4 = b*2+h, 2 = tensor {k,v}), block 128.
// Each CTA: 16 (or 15) overlapping nb blocks for one (b,h,tensor).
// out[b,nb,h,d] = sum_e x_block[e]*w[e,d] + pec[d],  pec = sum_e pe[e]*w[e,d]
// Thread layout: dvec = tid&31 (float4 over D), ep = tid>>5 (4-way split of blk).
// ---------------------------------------------------------------------------
__global__ __launch_bounds__(128, 1)
void compress_kernel(const float* __restrict__ kin, const float* __restrict__ vin,
                     const float* __restrict__ wk,  const float* __restrict__ wv,
                     const float* __restrict__ pek, const float* __restrict__ pev)
{
    extern __shared__ float xs[];            // 272*128 floats = 139,264 B

    const int nbg = blockIdx.x;              // 0..15
    const int bh  = blockIdx.y;              // b*2+h
    const int b   = bh >> 1, h = bh & 1;
    const int t   = blockIdx.z;              // 0=k, 1=v

    const float* x  = t ? vin : kin;
    const float* w  = t ? wv  : wk;
    const float* pe = t ? pev : pek;
    float* outp     = t ? g_vc : g_kc;

    const int tid  = threadIdx.x;
    const int dvec = tid & 31;               // float4 index over D (d = dvec*4)
    const int ep   = tid >> 5;               // 0..3, splits blk range

    const int nb0  = nbg * 16;
    const int JN   = (nbg == 15) ? 15 : 16;  // nb count in this group
    const int R    = JN * 16 + 16;           // rows of x needed
    const int row0 = nbg * 256;

    // Stage x rows [row0, row0+R) into smem (coalesced)
    for (int i = tid; i < R * 128; i += 128) {
        int r = i >> 7, dd = i & 127;
        xs[i] = x[((b * SEQ + row0 + r) * HKV + h) * DIM + dd];
    }
    __syncthreads();

    float4 acc[16];
#pragma unroll
    for (int j = 0; j < 16; ++j) acc[j] = make_float4(0.f, 0.f, 0.f, 0.f);
    float4 pec = make_float4(0.f, 0.f, 0.f, 0.f);

    const float4* w4 = (const float4*)w;     // w[e*128 + d] -> w4[e*32 + dvec]

    for (int blk = ep * 8; blk < ep * 8 + 8; ++blk) {
        const float*  xb  = xs + blk * 128;
        const float*  peb = pe + blk * 128;
        const float4* wb  = w4 + (size_t)blk * 128 * 32;
#pragma unroll 4
        for (int dd = 0; dd < 128; ++dd) {
            float4 wv4 = wb[dd * 32 + dvec];
            float  pv  = peb[dd];
            pec.x += pv * wv4.x; pec.y += pv * wv4.y;
            pec.z += pv * wv4.z; pec.w += pv * wv4.w;
#pragma unroll
            for (int j = 0; j < 16; ++j) {
                float xv = xb[j * 2048 + dd];   // row = j*16+blk (broadcast LDS)
                acc[j].x += xv * wv4.x; acc[j].y += xv * wv4.y;
                acc[j].z += xv * wv4.z; acc[j].w += xv * wv4.w;
            }
        }
    }

    // Cross-ep reduction through smem (reuse xs region)
    __syncthreads();
    float4* red = (float4*)xs;

    red[tid] = pec;
    __syncthreads();
    float4 pecT = make_float4(0.f, 0.f, 0.f, 0.f);
    if (ep == 0) {
        float4 a0 = red[dvec], a1 = red[32 + dvec], a2 = red[64 + dvec], a3 = red[96 + dvec];
        pecT.x = a0.x + a1.x + a2.x + a3.x;
        pecT.y = a0.y + a1.y + a2.y + a3.y;
        pecT.z = a0.z + a1.z + a2.z + a3.z;
        pecT.w = a0.w + a1.w + a2.w + a3.w;
    }
    __syncthreads();

    for (int j = 0; j < 16; ++j) {
        red[tid] = acc[j];
        __syncthreads();
        if (ep == 0 && j < JN) {
            float4 a0 = red[dvec], a1 = red[32 + dvec], a2 = red[64 + dvec], a3 = red[96 + dvec];
            float4 r4;
            r4.x = a0.x + a1.x + a2.x + a3.x + pecT.x;
            r4.y = a0.y + a1.y + a2.y + a3.y + pecT.y;
            r4.z = a0.z + a1.z + a2.z + a3.z + pecT.z;
            r4.w = a0.w + a1.w + a2.w + a3.w + pecT.w;
            int nb = nb0 + j;
            float4* o = (float4*)(outp + ((b * NBL + nb) * HKV + h) * DIM);
            o[dvec] = r4;
        }
        __syncthreads();
    }
}

// ---------------------------------------------------------------------------
// Attention kernel.
// grid (32 s-tiles, 16 g, 4 = b*2+h), block 512.
// Per CTA: 128 q-rows x 255 nb. Phase A: scores GEMM (8x8 reg tile).
// Softmax in smem (causal mask by row). Write attn_prob. Phase C: PV GEMM.
// smem: Psm[128][257] | Qs[128*32] | Ks[256*33]; Vs reuses Qs.
// ---------------------------------------------------------------------------
__global__ __launch_bounds__(512, 1)
void attn_kernel(const float* __restrict__ q, float* __restrict__ out,
                 float* __restrict__ attn, int write_attn)
{
    extern __shared__ float sm[];
    float* Psm = sm;                          // 128*257 floats
    float* Qs  = sm + 128 * 257;              // 128*32
    float* Ks  = Qs + 128 * 32;               // 256*33
    float* Vs  = Qs;                          // reuse after phase A

    const int st = blockIdx.x;                // s tile
    const int g  = blockIdx.y;
    const int bh = blockIdx.z;
    const int b  = bh >> 1, h = bh & 1;
    const int hq = h * GRP + g;
    const int s0 = st * 128;
    const int tid = threadIdx.x;

    const int rg = tid >> 5;                  // 0..15 (row group)
    const int cg = tid & 31;                  // 0..31 (col lane)

    const int kvbase = (b * NBL * HKV + h) * DIM;   // + nb*HKV*DIM + d

    // ---- Phase A: scores = Q (128xD) x Kc^T (D x 255) ----
    float acc[8][8];
#pragma unroll
    for (int i = 0; i < 8; ++i)
#pragma unroll
        for (int j = 0; j < 8; ++j) acc[i][j] = 0.f;

    for (int kc0 = 0; kc0 < DIM; kc0 += 32) {
        for (int i = tid; i < 128 * 32; i += 512) {
            int r = i >> 5, dd = i & 31;
            Qs[i] = q[((size_t)(b * SEQ + s0 + r) * HQN + hq) * DIM + kc0 + dd];
        }
        for (int i = tid; i < 256 * 32; i += 512) {
            int nbr = i >> 5, dd = i & 31;
            float vv = 0.f;
            if (nbr < NBL) vv = g_kc[kvbase + nbr * HKV * DIM + kc0 + dd];
            Ks[nbr * 33 + dd] = vv;
        }
        __syncthreads();
#pragma unroll 4
        for (int kk = 0; kk < 32; ++kk) {
            float a[8], bb[8];
#pragma unroll
            for (int i = 0; i < 8; ++i) a[i] = Qs[(rg + 16 * i) * 32 + kk];   // broadcast
#pragma unroll
            for (int j = 0; j < 8; ++j) bb[j] = Ks[(cg + 32 * j) * 33 + kk]; // conflict-free
#pragma unroll
            for (int i = 0; i < 8; ++i)
#pragma unroll
                for (int j = 0; j < 8; ++j)
                    acc[i][j] += a[i] * bb[j];
        }
        __syncthreads();
    }

    // Store scaled scores to Psm (padded stride 257)
#pragma unroll
    for (int i = 0; i < 8; ++i)
#pragma unroll
        for (int j = 0; j < 8; ++j)
            Psm[(rg + 16 * i) * 257 + cg + 32 * j] = acc[i][j] * SCALE;
    __syncthreads();

    // ---- Softmax: one row per thread, 128 active threads ----
    if (tid < 128) {
        int s = s0 + tid;
        int nvalid = (s >= 31) ? (((s - 31) >> 4) + 1) : 0;   // <= 255
        float* row = Psm + tid * 257;
        float m = -1e30f;
        for (int c = 0; c < nvalid; ++c) m = fmaxf(m, row[c]);
        float sum = 0.f;
        for (int c = 0; c < 256; ++c) {
            float e = 0.f;
            if (c < nvalid) { e = __expf(row[c] - m); sum += e; }
            row[c] = e;
        }
        float inv = 1.f / fmaxf(sum, 1e-20f);
        for (int c = 0; c < 256; ++c) row[c] *= inv;
    }
    __syncthreads();

    // ---- Write attn probabilities: (BS, HQ, S, NB), coalesced ----
    if (write_attn) {
        size_t abase = (((size_t)b * HQN + hq) * SEQ + s0) * NBL;
        for (int i = tid; i < 128 * NBL; i += 512) {
            int r = i / NBL;
            int c = i - r * NBL;
            attn[abase + i] = Psm[r * 257 + c];
        }
    }

    // ---- Phase C: out = P (128x255) x Vc (255x128) ----
    float oacc[8][4];
#pragma unroll
    for (int i = 0; i < 8; ++i)
#pragma unroll
        for (int j = 0; j < 4; ++j) oacc[i][j] = 0.f;

    for (int mc = 0; mc < 8; ++mc) {
        __syncthreads();   // protect Vs from readers of previous chunk / Qs reuse
        for (int i = tid; i < 32 * 128; i += 512) {
            int m_ = i >> 7, dd = i & 127;
            int nb = mc * 32 + m_;
            Vs[i] = (nb < NBL) ? g_vc[kvbase + nb * HKV * DIM + dd] : 0.f;
        }
        __syncthreads();
#pragma unroll 4
        for (int mm = 0; mm < 32; ++mm) {
            int col = mc * 32 + mm;
            float a[8], bb[4];
#pragma unroll
            for (int i = 0; i < 8; ++i) a[i] = Psm[(rg + 16 * i) * 257 + col];  // broadcast
#pragma unroll
            for (int j = 0; j < 4; ++j) bb[j] = Vs[mm * 128 + cg + 32 * j];     // conflict-free
#pragma unroll
            for (int i = 0; i < 8; ++i)
#pragma unroll
                for (int j = 0; j < 4; ++j)
                    oacc[i][j] += a[i] * bb[j];
        }
    }

    // ---- Store out: (BS, S, HQ, D), coalesced across cg ----
#pragma unroll
    for (int i = 0; i < 8; ++i) {
        int s = s0 + rg + 16 * i;
        size_t obase = ((size_t)(b * SEQ + s) * HQN + hq) * DIM;
#pragma unroll
        for (int j = 0; j < 4; ++j)
            out[obase + cg + 32 * j] = oacc[i][j];
    }
}

// ---------------------------------------------------------------------------
extern "C" void kernel_launch(void* const* d_in, const int* in_sizes, int n_in,
                              void* d_out, int out_size)
{
    const float* q   = (const float*)d_in[0];
    const float* k   = (const float*)d_in[1];
    const float* v   = (const float*)d_in[2];
    // d_in[3] = cu_seqlens_k (fixed [0,S,2S]) — unused
    const float* wk  = (const float*)d_in[4];
    const float* wv  = (const float*)d_in[5];
    const float* pek = (const float*)d_in[6];
    const float* pev = (const float*)d_in[7];

    float* out  = (float*)d_out;
    float* attn = out + OUT_ELEMS;
    int write_attn = ((size_t)out_size >= OUT_ELEMS + ATTN_ELEMS) ? 1 : 0;

    const int COMP_SMEM = 272 * 128 * 4;                       // 139,264 B
    const int ATT_SMEM  = (128 * 257 + 128 * 32 + 256 * 33) * 4; // 181,760 B

    cudaFuncSetAttribute(compress_kernel,
                         cudaFuncAttributeMaxDynamicSharedMemorySize, COMP_SMEM);
    cudaFuncSetAttribute(attn_kernel,
                         cudaFuncAttributeMaxDynamicSharedMemorySize, ATT_SMEM);

    compress_kernel<<<dim3(16, 4, 2), 128, COMP_SMEM>>>(k, v, wk, wv, pek, pev);
    attn_kernel<<<dim3(32, 16, 4), 512, ATT_SMEM>>>(q, out, attn, write_attn);
}

// round 4
// speedup vs baseline: 1.3302x; 1.3302x over previous
#include <cuda_runtime.h>

// Problem constants (fixed by reference setup)
#define BSZ     2
#define SEQ     4096
#define HQN     32
#define HKV     2
#define DIM     128
#define NBL     255
#define GRP     16
#define SCALE   0.08838834764831845f   // 1/sqrt(128)

#define OUT_ELEMS  ((size_t)BSZ*SEQ*HQN*DIM)            // 33,554,432
#define ATTN_ELEMS ((size_t)BSZ*HQN*SEQ*NBL)            // 66,846,720

typedef unsigned long long ull;

// Scratch for compressed K/V: (BS, NB, HKV, D)
__device__ float g_kc[BSZ*NBL*HKV*DIM];
__device__ float g_vc[BSZ*NBL*HKV*DIM];

// ---- packed f32x2 helpers (sm_103a) --------------------------------------
__device__ __forceinline__ ull pack2(float lo, float hi) {
    ull r; asm("mov.b64 %0,{%1,%2};" : "=l"(r) : "f"(lo), "f"(hi)); return r;
}
__device__ __forceinline__ void unpack2(ull v, float& lo, float& hi) {
    asm("mov.b64 {%0,%1},%2;" : "=f"(lo), "=f"(hi) : "l"(v));
}
__device__ __forceinline__ ull ffma2(ull a, ull b, ull c) {
    ull d; asm("fma.rn.f32x2 %0,%1,%2,%3;" : "=l"(d) : "l"(a), "l"(b), "l"(c)); return d;
}
__device__ __forceinline__ ull fadd2(ull a, ull b) {
    ull d; asm("add.rn.f32x2 %0,%1,%2;" : "=l"(d) : "l"(a), "l"(b)); return d;
}

// ---------------------------------------------------------------------------
// Compression kernel. grid (16, 4, 2), block 256.
// out[b,nb,h,d] = sum_e x_block[e]*w[e,d] + pec[d],  pec = sum_e pe[e]*w[e,d]
// dvec = tid&31 (4 d-floats = 2 f32x2 lanes), ep = tid>>5 (8-way blk split).
// Inner loop per (blk,dd): 1 LDG.128(w pair), 16 broadcast LDS(x), 17 packs,
// 34 FFMA2  -> issue-bound right at the halved FFMA2 pipe floor.
// ---------------------------------------------------------------------------
__global__ __launch_bounds__(256, 1)
void compress_kernel(const float* __restrict__ kin, const float* __restrict__ vin,
                     const float* __restrict__ wk,  const float* __restrict__ wv,
                     const float* __restrict__ pek, const float* __restrict__ pev)
{
    extern __shared__ float xs[];            // 272*128 floats = 139,264 B

    const int nbg = blockIdx.x;              // 0..15
    const int bh  = blockIdx.y;              // b*2+h
    const int b   = bh >> 1, h = bh & 1;
    const int t   = blockIdx.z;              // 0=k, 1=v

    const float* x  = t ? vin : kin;
    const float* w  = t ? wv  : wk;
    const float* pe = t ? pev : pek;
    float* outp     = t ? g_vc : g_kc;

    const int tid  = threadIdx.x;
    const int dvec = tid & 31;               // float4 index over D
    const int ep   = tid >> 5;               // 0..7, 4 blks each

    const int nb0  = nbg * 16;
    const int JN   = (nbg == 15) ? 15 : 16;
    const int R    = JN * 16 + 16;
    const int row0 = nbg * 256;

    for (int i = tid; i < R * 128; i += 256) {
        int r = i >> 7, dd = i & 127;
        xs[i] = x[((b * SEQ + row0 + r) * HKV + h) * DIM + dd];
    }
    __syncthreads();

    ull acc[16][2];
#pragma unroll
    for (int j = 0; j < 16; ++j) { acc[j][0] = 0ull; acc[j][1] = 0ull; }
    ull pec0 = 0ull, pec1 = 0ull;

    for (int bq = 0; bq < 4; ++bq) {
        const int blk = ep * 4 + bq;
        const float* xb  = xs + blk * 128;
        const float* peb = pe + blk * 128;
        const ull* wrow = (const ull*)w + (size_t)blk * 8192 + dvec * 2;
#pragma unroll 2
        for (int dd = 0; dd < 128; ++dd) {
            ulonglong2 w2 = *(const ulonglong2*)(wrow + (size_t)dd * 64);
            float pv = peb[dd];
            ull pv2 = pack2(pv, pv);
            pec0 = ffma2(pv2, w2.x, pec0);
            pec1 = ffma2(pv2, w2.y, pec1);
#pragma unroll
            for (int j = 0; j < 16; ++j) {
                float xv = xb[j * 2048 + dd];     // broadcast LDS
                ull x2 = pack2(xv, xv);
                acc[j][0] = ffma2(x2, w2.x, acc[j][0]);
                acc[j][1] = ffma2(x2, w2.y, acc[j][1]);
            }
        }
    }

    // 8-way cross-ep reduction through smem (reuse xs)
    __syncthreads();
    ull* red = (ull*)xs;

    red[tid * 2]     = pec0;
    red[tid * 2 + 1] = pec1;
    __syncthreads();
    ull pt0 = 0ull, pt1 = 0ull;
    if (ep == 0) {
#pragma unroll
        for (int e8 = 0; e8 < 8; ++e8) {
            pt0 = fadd2(pt0, red[(e8 * 32 + dvec) * 2]);
            pt1 = fadd2(pt1, red[(e8 * 32 + dvec) * 2 + 1]);
        }
    }
    __syncthreads();

    for (int j = 0; j < 16; ++j) {
        red[tid * 2]     = acc[j][0];
        red[tid * 2 + 1] = acc[j][1];
        __syncthreads();
        if (ep == 0 && j < JN) {
            ull s0v = pt0, s1v = pt1;
#pragma unroll
            for (int e8 = 0; e8 < 8; ++e8) {
                s0v = fadd2(s0v, red[(e8 * 32 + dvec) * 2]);
                s1v = fadd2(s1v, red[(e8 * 32 + dvec) * 2 + 1]);
            }
            float d0, d1, d2, d3;
            unpack2(s0v, d0, d1);
            unpack2(s1v, d2, d3);
            float4* o = (float4*)(outp + ((b * NBL + nb0 + j) * HKV + h) * DIM);
            o[dvec] = make_float4(d0, d1, d2, d3);
        }
        __syncthreads();
    }
}

// ---------------------------------------------------------------------------
// Attention kernel. grid (32 s-tiles, 16 g, 4 = b*2+h), block 512.
// Rows per thread: rg+16i (i=0..7). Phase A col pairs {cg+64p, cg+64p+32}.
// Phase A: dup-stored Q (LDS.64 bcast) x pair-transposed K (LDS.64) -> FFMA2.
// Softmax entirely in registers via warp shuffles; attn written from regs.
// Phase C: f32x2 pairs along the mm reduction dim; V transposed [d][mm].
// smem: Psm[128][258] | { Qsd[128][33]f2 + Kp2[32][129]f2 } / Vt[128][34]
// ---------------------------------------------------------------------------
__global__ __launch_bounds__(512, 1)
void attn_kernel(const float* __restrict__ q, float* __restrict__ out,
                 float* __restrict__ attn, int write_attn)
{
    extern __shared__ float sm[];
    float*  Psm = sm;                         // 128*258 floats
    float2* Qsd = (float2*)(sm + 33024);      // [128][33] dup pairs
    float2* Kp2 = (float2*)(sm + 41472);      // [32][129] col pairs
    float*  Vt  = sm + 33024;                 // [128][34] (phase C, reuse)

    const int st = blockIdx.x;
    const int g  = blockIdx.y;
    const int bh = blockIdx.z;
    const int b  = bh >> 1, h = bh & 1;
    const int hq = h * GRP + g;
    const int s0 = st * 128;
    const int tid = threadIdx.x;
    const int rg  = tid >> 5;                 // 0..15
    const int cg  = tid & 31;                 // 0..31

    const int kvbase = (b * NBL * HKV + h) * DIM;

    // ---- Phase A: scores = Q (128xD) x Kc^T, col-paired f32x2 ----
    ull acc[8][4];
#pragma unroll
    for (int i = 0; i < 8; ++i)
#pragma unroll
        for (int p = 0; p < 4; ++p) acc[i][p] = 0ull;

    for (int c4 = 0; c4 < 4; ++c4) {
        const int kc0 = c4 * 32;
        for (int i = tid; i < 128 * 32; i += 512) {
            int r = i >> 5, kk = i & 31;
            float qv = q[((size_t)((b * SEQ + s0 + r) * HQN + hq)) * DIM + kc0 + kk];
            Qsd[r * 33 + kk] = make_float2(qv, qv);
        }
        for (int i = tid; i < 256 * 32; i += 512) {
            int c = i >> 5, kk = i & 31;
            float kvv = (c < NBL) ? g_kc[kvbase + c * (HKV * DIM) + kc0 + kk] : 0.f;
            int pc   = (c & 31) + 32 * (c >> 6);
            int half = (c >> 5) & 1;
            ((float*)(Kp2 + kk * 129 + pc))[half] = kvv;
        }
        __syncthreads();
#pragma unroll 4
        for (int kk = 0; kk < 32; ++kk) {
            ull a2[8], b2[4];
#pragma unroll
            for (int i = 0; i < 8; ++i)
                a2[i] = *(const ull*)(Qsd + (rg + 16 * i) * 33 + kk);   // bcast LDS.64
#pragma unroll
            for (int p = 0; p < 4; ++p)
                b2[p] = *(const ull*)(Kp2 + kk * 129 + p * 32 + cg);    // conflict-free
#pragma unroll
            for (int i = 0; i < 8; ++i)
#pragma unroll
                for (int p = 0; p < 4; ++p)
                    acc[i][p] = ffma2(a2[i], b2[p], acc[i][p]);
        }
        __syncthreads();
    }

    // ---- Softmax in registers (warp-shuffle row reductions) ----
    const size_t abase = (((size_t)b * HQN + hq) * SEQ + s0) * NBL;
#pragma unroll
    for (int i = 0; i < 8; ++i) {
        const int r = rg + 16 * i;
        const int s = s0 + r;
        const int nv = (s >= 31) ? (((s - 31) >> 4) + 1) : 0;
        float v[8];
#pragma unroll
        for (int p = 0; p < 4; ++p) {
            float lo, hi; unpack2(acc[i][p], lo, hi);
            v[2 * p]     = lo * SCALE;    // col cg+64p
            v[2 * p + 1] = hi * SCALE;    // col cg+64p+32
        }
        float m = -1e30f;
#pragma unroll
        for (int p = 0; p < 4; ++p) {
            int c0 = cg + 64 * p;
            if (c0 < nv)      m = fmaxf(m, v[2 * p]);
            if (c0 + 32 < nv) m = fmaxf(m, v[2 * p + 1]);
        }
#pragma unroll
        for (int off = 16; off >= 1; off >>= 1)
            m = fmaxf(m, __shfl_xor_sync(0xffffffffu, m, off));
        float ssum = 0.f;
#pragma unroll
        for (int p = 0; p < 4; ++p) {
            int c0 = cg + 64 * p;
            float e0 = (c0 < nv)      ? __expf(v[2 * p] - m)     : 0.f;
            float e1 = (c0 + 32 < nv) ? __expf(v[2 * p + 1] - m) : 0.f;
            v[2 * p] = e0; v[2 * p + 1] = e1;
            ssum += e0 + e1;
        }
#pragma unroll
        for (int off = 16; off >= 1; off >>= 1)
            ssum += __shfl_xor_sync(0xffffffffu, ssum, off);
        const float inv = 1.f / fmaxf(ssum, 1e-20f);
        float* prow = Psm + r * 258;
#pragma unroll
        for (int p = 0; p < 4; ++p) {
            int c0 = cg + 64 * p, c1 = c0 + 32;
            float p0 = v[2 * p] * inv, p1 = v[2 * p + 1] * inv;
            prow[c0] = p0;
            prow[c1] = p1;
            if (write_attn) {
                attn[abase + (size_t)r * NBL + c0] = p0;            // c0 <= 223
                if (c1 < NBL) attn[abase + (size_t)r * NBL + c1] = p1;
            }
        }
    }
    __syncthreads();

    // ---- Phase C: out = P (128x255) x Vc (255x128), mm-paired f32x2 ----
    ull oacc[8][4];
#pragma unroll
    for (int i = 0; i < 8; ++i)
#pragma unroll
        for (int j = 0; j < 4; ++j) oacc[i][j] = 0ull;

    for (int mc = 0; mc < 8; ++mc) {
        __syncthreads();
        for (int i = tid; i < 32 * 128; i += 512) {
            int mm = i >> 7, dd = i & 127;
            int nb = mc * 32 + mm;
            Vt[dd * 34 + mm] = (nb < NBL) ? g_vc[kvbase + nb * (HKV * DIM) + dd] : 0.f;
        }
        __syncthreads();
#pragma unroll 2
        for (int m2 = 0; m2 < 16; ++m2) {
            ull a2[8], b2[4];
#pragma unroll
            for (int i = 0; i < 8; ++i)
                a2[i] = *(const ull*)(Psm + (rg + 16 * i) * 258 + mc * 32 + 2 * m2); // bcast
#pragma unroll
            for (int j = 0; j < 4; ++j)
                b2[j] = *(const ull*)(Vt + (cg + 32 * j) * 34 + 2 * m2);             // cf
#pragma unroll
            for (int i = 0; i < 8; ++i)
#pragma unroll
                for (int j = 0; j < 4; ++j)
                    oacc[i][j] = ffma2(a2[i], b2[j], oacc[i][j]);
        }
    }

    // ---- Store out: (BS, S, HQ, D) ----
#pragma unroll
    for (int i = 0; i < 8; ++i) {
        int s = s0 + rg + 16 * i;
        size_t obase = ((size_t)(b * SEQ + s) * HQN + hq) * DIM;
#pragma unroll
        for (int j = 0; j < 4; ++j) {
            float lo, hi; unpack2(oacc[i][j], lo, hi);
            out[obase + cg + 32 * j] = lo + hi;
        }
    }
}

// ---------------------------------------------------------------------------
extern "C" void kernel_launch(void* const* d_in, const int* in_sizes, int n_in,
                              void* d_out, int out_size)
{
    const float* q   = (const float*)d_in[0];
    const float* k   = (const float*)d_in[1];
    const float* v   = (const float*)d_in[2];
    // d_in[3] = cu_seqlens_k (fixed [0,S,2S]) — unused
    const float* wk  = (const float*)d_in[4];
    const float* wv  = (const float*)d_in[5];
    const float* pek = (const float*)d_in[6];
    const float* pev = (const float*)d_in[7];

    float* out  = (float*)d_out;
    float* attn = out + OUT_ELEMS;
    int write_attn = ((size_t)out_size >= OUT_ELEMS + ATTN_ELEMS) ? 1 : 0;

    const int COMP_SMEM = 272 * 128 * 4;                         // 139,264 B
    const int ATT_SMEM  = (33024 + 8448 + 8256) * 4;             // 198,912 B

    cudaFuncSetAttribute(compress_kernel,
                         cudaFuncAttributeMaxDynamicSharedMemorySize, COMP_SMEM);
    cudaFuncSetAttribute(attn_kernel,
                         cudaFuncAttributeMaxDynamicSharedMemorySize, ATT_SMEM);

    compress_kernel<<<dim3(16, 4, 2), 256, COMP_SMEM>>>(k, v, wk, wv, pek, pev);
    attn_kernel<<<dim3(32, 16, 4), 512, ATT_SMEM>>>(q, out, attn, write_attn);
}

// round 5
// speedup vs baseline: 1.4382x; 1.0812x over previous
#include <cuda_runtime.h>

// Problem constants (fixed by reference setup)
#define BSZ     2
#define SEQ     4096
#define HQN     32
#define HKV     2
#define DIM     128
#define NBL     255
#define GRP     16
#define SCALE   0.08838834764831845f   // 1/sqrt(128)

#define OUT_ELEMS  ((size_t)BSZ*SEQ*HQN*DIM)            // 33,554,432
#define ATTN_ELEMS ((size_t)BSZ*HQN*SEQ*NBL)            // 66,846,720

typedef unsigned long long ull;

// Scratch for compressed K/V: (BS, NB, HKV, D)
__device__ float g_kc[BSZ*NBL*HKV*DIM];
__device__ float g_vc[BSZ*NBL*HKV*DIM];

// ---- packed f32x2 helpers (sm_103a) --------------------------------------
__device__ __forceinline__ ull pack2(float lo, float hi) {
    ull r; asm("mov.b64 %0,{%1,%2};" : "=l"(r) : "f"(lo), "f"(hi)); return r;
}
__device__ __forceinline__ void unpack2(ull v, float& lo, float& hi) {
    asm("mov.b64 {%0,%1},%2;" : "=f"(lo), "=f"(hi) : "l"(v));
}
__device__ __forceinline__ ull ffma2(ull a, ull b, ull c) {
    ull d; asm("fma.rn.f32x2 %0,%1,%2,%3;" : "=l"(d) : "l"(a), "l"(b), "l"(c)); return d;
}
__device__ __forceinline__ ull fadd2(ull a, ull b) {
    ull d; asm("add.rn.f32x2 %0,%1,%2;" : "=l"(d) : "l"(a), "l"(b)); return d;
}

// ---------------------------------------------------------------------------
// Compression kernel. grid (16, 4, 2), block 512 (16 warps -> 4/SMSP).
// out[b,nb,h,d] = sum_e x_block[e]*w[e,d] + pec[d],  pec = sum_e pe[e]*w[e,d]
// Thread split: dvec = tid&31 (4 d-floats), ep = (tid>>5)&3 (8 blks each),
//               jg = tid>>7 (4 nb-outputs each).  acc = 4 x 2 f32x2.
// ---------------------------------------------------------------------------
__global__ __launch_bounds__(512, 1)
void compress_kernel(const float* __restrict__ kin, const float* __restrict__ vin,
                     const float* __restrict__ wk,  const float* __restrict__ wv,
                     const float* __restrict__ pek, const float* __restrict__ pev)
{
    extern __shared__ float xs[];            // 272*128 floats = 139,264 B

    const int nbg = blockIdx.x;              // 0..15
    const int bh  = blockIdx.y;              // b*2+h
    const int b   = bh >> 1, h = bh & 1;
    const int t   = blockIdx.z;              // 0=k, 1=v

    const float* x  = t ? vin : kin;
    const float* w  = t ? wv  : wk;
    const float* pe = t ? pev : pek;
    float* outp     = t ? g_vc : g_kc;

    const int tid  = threadIdx.x;
    const int dvec = tid & 31;               // float4 index over D
    const int ep   = (tid >> 5) & 3;         // 0..3, 8 blks each
    const int jg   = tid >> 7;               // 0..3, 4 nb each

    const int nb0  = nbg * 16;
    const int JN   = (nbg == 15) ? 15 : 16;
    const int R    = JN * 16 + 16;
    const int row0 = nbg * 256;

    for (int i = tid; i < R * 128; i += 512) {
        int r = i >> 7, dd = i & 127;
        xs[i] = x[((b * SEQ + row0 + r) * HKV + h) * DIM + dd];
    }
    __syncthreads();

    ull acc[4][2];
#pragma unroll
    for (int j = 0; j < 4; ++j) { acc[j][0] = 0ull; acc[j][1] = 0ull; }
    ull pec0 = 0ull, pec1 = 0ull;

    for (int bq = 0; bq < 8; ++bq) {
        const int blk = ep * 8 + bq;
        const float* xb  = xs + jg * 8192 + blk * 128;   // + jj*2048 + dd
        const float* peb = pe + blk * 128;
        const ull*   wb  = (const ull*)w + (size_t)blk * 128 * 64 + dvec * 2;
#pragma unroll 2
        for (int dd = 0; dd < 128; ++dd) {
            ulonglong2 w2 = *(const ulonglong2*)(wb + (size_t)dd * 64);
            float pv = peb[dd];
            ull pv2 = pack2(pv, pv);
            pec0 = ffma2(pv2, w2.x, pec0);
            pec1 = ffma2(pv2, w2.y, pec1);
#pragma unroll
            for (int jj = 0; jj < 4; ++jj) {
                float xv = xb[jj * 2048 + dd];     // broadcast LDS
                ull x2 = pack2(xv, xv);
                acc[jj][0] = ffma2(x2, w2.x, acc[jj][0]);
                acc[jj][1] = ffma2(x2, w2.y, acc[jj][1]);
            }
        }
    }

    // 4-way cross-ep reduction (within each jg) through smem (reuse xs)
    __syncthreads();
    ull* red = (ull*)xs;                      // 512*2 ull = 8 KB

    red[tid * 2]     = pec0;
    red[tid * 2 + 1] = pec1;
    __syncthreads();
    ull pt0 = 0ull, pt1 = 0ull;
    if (ep == 0) {
#pragma unroll
        for (int e4 = 0; e4 < 4; ++e4) {
            int src = jg * 128 + e4 * 32 + dvec;
            pt0 = fadd2(pt0, red[src * 2]);
            pt1 = fadd2(pt1, red[src * 2 + 1]);
        }
    }
    __syncthreads();

    for (int jj = 0; jj < 4; ++jj) {
        red[tid * 2]     = acc[jj][0];
        red[tid * 2 + 1] = acc[jj][1];
        __syncthreads();
        if (ep == 0) {
            ull s0v = pt0, s1v = pt1;
#pragma unroll
            for (int e4 = 0; e4 < 4; ++e4) {
                int src = jg * 128 + e4 * 32 + dvec;
                s0v = fadd2(s0v, red[src * 2]);
                s1v = fadd2(s1v, red[src * 2 + 1]);
            }
            int nb = nb0 + jg * 4 + jj;
            if (nb < NBL) {
                float d0, d1, d2, d3;
                unpack2(s0v, d0, d1);
                unpack2(s1v, d2, d3);
                float4* o = (float4*)(outp + ((b * NBL + nb) * HKV + h) * DIM);
                o[dvec] = make_float4(d0, d1, d2, d3);
            }
        }
        __syncthreads();
    }
}

// ---------------------------------------------------------------------------
// Attention kernel. grid (32 s-tiles, 16 g, 4 = b*2+h), block 512.
// Causal chunk skipping: tile st has NVC = 8*st+7 valid columns max.
// Phase A processes only 64-col chunks p <= pmax; phase C only 32-col
// chunks mc <= mcmax. Masked P entries are exactly 0 (attn still written).
// ---------------------------------------------------------------------------
__global__ __launch_bounds__(512, 1)
void attn_kernel(const float* __restrict__ q, float* __restrict__ out,
                 float* __restrict__ attn, int write_attn)
{
    extern __shared__ float sm[];
    float*  Psm = sm;                         // 128*258 floats
    float2* Qsd = (float2*)(sm + 33024);      // [128][33] dup pairs
    float2* Kp2 = (float2*)(sm + 41472);      // [32][129] col pairs
    float*  Vt  = sm + 33024;                 // [128][34] (phase C, reuse)

    const int st = blockIdx.x;
    const int g  = blockIdx.y;
    const int bh = blockIdx.z;
    const int b  = bh >> 1, h = bh & 1;
    const int hq = h * GRP + g;
    const int s0 = st * 128;
    const int tid = threadIdx.x;
    const int rg  = tid >> 5;                 // 0..15
    const int cg  = tid & 31;                 // 0..31

    const int kvbase = (b * NBL * HKV + h) * DIM;

    const int NVC   = st * 8 + 7;                       // max valid col count
    const int pmax  = min(3, (NVC - 1) >> 6);           // live 64-col chunks
    const int mcmax = min(7, (NVC - 1) >> 5);           // live 32-col chunks

    // ---- Phase A: scores = Q (128xD) x Kc^T, col-paired f32x2 ----
    ull acc[8][4];
#pragma unroll
    for (int i = 0; i < 8; ++i)
#pragma unroll
        for (int p = 0; p < 4; ++p) acc[i][p] = 0ull;

    const int kcols = (pmax + 1) * 64;        // columns actually staged

    for (int c4 = 0; c4 < 4; ++c4) {
        const int kc0 = c4 * 32;
        for (int i = tid; i < 128 * 32; i += 512) {
            int r = i >> 5, kk = i & 31;
            float qv = q[((size_t)((b * SEQ + s0 + r) * HQN + hq)) * DIM + kc0 + kk];
            Qsd[r * 33 + kk] = make_float2(qv, qv);
        }
        for (int i = tid; i < kcols * 32; i += 512) {
            int c = i >> 5, kk = i & 31;
            float kvv = (c < NBL) ? g_kc[kvbase + c * (HKV * DIM) + kc0 + kk] : 0.f;
            int pc   = (c & 31) + 32 * (c >> 6);
            int half = (c >> 5) & 1;
            ((float*)(Kp2 + kk * 129 + pc))[half] = kvv;
        }
        __syncthreads();
#pragma unroll 4
        for (int kk = 0; kk < 32; ++kk) {
            ull a2[8];
#pragma unroll
            for (int i = 0; i < 8; ++i)
                a2[i] = *(const ull*)(Qsd + (rg + 16 * i) * 33 + kk);   // bcast LDS.64
#pragma unroll
            for (int p = 0; p < 4; ++p) {
                if (p <= pmax) {
                    ull b2 = *(const ull*)(Kp2 + kk * 129 + p * 32 + cg); // conflict-free
#pragma unroll
                    for (int i = 0; i < 8; ++i)
                        acc[i][p] = ffma2(a2[i], b2, acc[i][p]);
                }
            }
        }
        __syncthreads();
    }

    // ---- Softmax in registers (warp-shuffle row reductions) ----
    // acc[p > pmax] stayed 0; those columns are >= NVC >= nv, so masking
    // by c < nv handles them without special cases.
    const size_t abase = (((size_t)b * HQN + hq) * SEQ + s0) * NBL;
#pragma unroll
    for (int i = 0; i < 8; ++i) {
        const int r = rg + 16 * i;
        const int s = s0 + r;
        const int nv = (s >= 31) ? (((s - 31) >> 4) + 1) : 0;
        float v[8];
#pragma unroll
        for (int p = 0; p < 4; ++p) {
            float lo, hi; unpack2(acc[i][p], lo, hi);
            v[2 * p]     = lo * SCALE;    // col cg+64p
            v[2 * p + 1] = hi * SCALE;    // col cg+64p+32
        }
        float m = -1e30f;
#pragma unroll
        for (int p = 0; p < 4; ++p) {
            int c0 = cg + 64 * p;
            if (c0 < nv)      m = fmaxf(m, v[2 * p]);
            if (c0 + 32 < nv) m = fmaxf(m, v[2 * p + 1]);
        }
#pragma unroll
        for (int off = 16; off >= 1; off >>= 1)
            m = fmaxf(m, __shfl_xor_sync(0xffffffffu, m, off));
        float ssum = 0.f;
#pragma unroll
        for (int p = 0; p < 4; ++p) {
            int c0 = cg + 64 * p;
            float e0 = (c0 < nv)      ? __expf(v[2 * p] - m)     : 0.f;
            float e1 = (c0 + 32 < nv) ? __expf(v[2 * p + 1] - m) : 0.f;
            v[2 * p] = e0; v[2 * p + 1] = e1;
            ssum += e0 + e1;
        }
#pragma unroll
        for (int off = 16; off >= 1; off >>= 1)
            ssum += __shfl_xor_sync(0xffffffffu, ssum, off);
        const float inv = 1.f / fmaxf(ssum, 1e-20f);
        float* prow = Psm + r * 258;
#pragma unroll
        for (int p = 0; p < 4; ++p) {
            int c0 = cg + 64 * p, c1 = c0 + 32;
            float p0 = v[2 * p] * inv, p1 = v[2 * p + 1] * inv;
            prow[c0] = p0;
            prow[c1] = p1;
            if (write_attn) {
                attn[abase + (size_t)r * NBL + c0] = p0;            // c0 <= 223
                if (c1 < NBL) attn[abase + (size_t)r * NBL + c1] = p1;
            }
        }
    }
    __syncthreads();

    // ---- Phase C: out = P (128x255) x Vc (255x128), mm-paired f32x2 ----
    ull oacc[8][4];
#pragma unroll
    for (int i = 0; i < 8; ++i)
#pragma unroll
        for (int j = 0; j < 4; ++j) oacc[i][j] = 0ull;

    for (int mc = 0; mc <= mcmax; ++mc) {
        __syncthreads();
        for (int i = tid; i < 32 * 128; i += 512) {
            int mm = i >> 7, dd = i & 127;
            int nb = mc * 32 + mm;
            Vt[dd * 34 + mm] = (nb < NBL) ? g_vc[kvbase + nb * (HKV * DIM) + dd] : 0.f;
        }
        __syncthreads();
#pragma unroll 2
        for (int m2 = 0; m2 < 16; ++m2) {
            ull a2[8], b2[4];
#pragma unroll
            for (int i = 0; i < 8; ++i)
                a2[i] = *(const ull*)(Psm + (rg + 16 * i) * 258 + mc * 32 + 2 * m2); // bcast
#pragma unroll
            for (int j = 0; j < 4; ++j)
                b2[j] = *(const ull*)(Vt + (cg + 32 * j) * 34 + 2 * m2);             // cf
#pragma unroll
            for (int i = 0; i < 8; ++i)
#pragma unroll
                for (int j = 0; j < 4; ++j)
                    oacc[i][j] = ffma2(a2[i], b2[j], oacc[i][j]);
        }
    }

    // ---- Store out: (BS, S, HQ, D) ----
#pragma unroll
    for (int i = 0; i < 8; ++i) {
        int s = s0 + rg + 16 * i;
        size_t obase = ((size_t)(b * SEQ + s) * HQN + hq) * DIM;
#pragma unroll
        for (int j = 0; j < 4; ++j) {
            float lo, hi; unpack2(oacc[i][j], lo, hi);
            out[obase + cg + 32 * j] = lo + hi;
        }
    }
}

// ---------------------------------------------------------------------------
extern "C" void kernel_launch(void* const* d_in, const int* in_sizes, int n_in,
                              void* d_out, int out_size)
{
    const float* q   = (const float*)d_in[0];
    const float* k   = (const float*)d_in[1];
    const float* v   = (const float*)d_in[2];
    // d_in[3] = cu_seqlens_k (fixed [0,S,2S]) — unused
    const float* wk  = (const float*)d_in[4];
    const float* wv  = (const float*)d_in[5];
    const float* pek = (const float*)d_in[6];
    const float* pev = (const float*)d_in[7];

    float* out  = (float*)d_out;
    float* attn = out + OUT_ELEMS;
    int write_attn = ((size_t)out_size >= OUT_ELEMS + ATTN_ELEMS) ? 1 : 0;

    const int COMP_SMEM = 272 * 128 * 4;                         // 139,264 B
    const int ATT_SMEM  = (33024 + 8448 + 8256) * 4;             // 198,912 B

    cudaFuncSetAttribute(compress_kernel,
                         cudaFuncAttributeMaxDynamicSharedMemorySize, COMP_SMEM);
    cudaFuncSetAttribute(attn_kernel,
                         cudaFuncAttributeMaxDynamicSharedMemorySize, ATT_SMEM);

    compress_kernel<<<dim3(16, 4, 2), 512, COMP_SMEM>>>(k, v, wk, wv, pek, pev);
    attn_kernel<<<dim3(32, 16, 4), 512, ATT_SMEM>>>(q, out, attn, write_attn);
}

// round 6
// speedup vs baseline: 1.8240x; 1.2682x over previous
#include <cuda_runtime.h>

// Problem constants (fixed by reference setup)
#define BSZ     2
#define SEQ     4096
#define HQN     32
#define HKV     2
#define DIM     128
#define NBL     255
#define GRP     16
#define SCALE   0.08838834764831845f   // 1/sqrt(128)

#define OUT_ELEMS  ((size_t)BSZ*SEQ*HQN*DIM)            // 33,554,432
#define ATTN_ELEMS ((size_t)BSZ*HQN*SEQ*NBL)            // 66,846,720

typedef unsigned long long ull;

// Scratch for compressed K/V: (BS, NB, HKV, D)
__device__ float g_kc[BSZ*NBL*HKV*DIM];
__device__ float g_vc[BSZ*NBL*HKV*DIM];

// ---- packed f32x2 helpers (sm_103a) --------------------------------------
__device__ __forceinline__ ull pack2(float lo, float hi) {
    ull r; asm("mov.b64 %0,{%1,%2};" : "=l"(r) : "f"(lo), "f"(hi)); return r;
}
__device__ __forceinline__ void unpack2(ull v, float& lo, float& hi) {
    asm("mov.b64 {%0,%1},%2;" : "=f"(lo), "=f"(hi) : "l"(v));
}
__device__ __forceinline__ ull ffma2(ull a, ull b, ull c) {
    ull d; asm("fma.rn.f32x2 %0,%1,%2,%3;" : "=l"(d) : "l"(a), "l"(b), "l"(c)); return d;
}
__device__ __forceinline__ ull fadd2(ull a, ull b) {
    ull d; asm("add.rn.f32x2 %0,%1,%2;" : "=l"(d) : "l"(a), "l"(b)); return d;
}

// ---------------------------------------------------------------------------
// Compression kernel. grid (16, 4, 2), block 512 (16 warps).
// NO W replication: thread (ep, dvec) covers 2 blocks x 4 d-floats, all 16
// nb-outputs -> W L2 traffic 2.1 MB/CTA. Single-pass 16-way reduction in smem.
// ---------------------------------------------------------------------------
__global__ __launch_bounds__(512, 1)
void compress_kernel(const float* __restrict__ kin, const float* __restrict__ vin,
                     const float* __restrict__ wk,  const float* __restrict__ wv,
                     const float* __restrict__ pek, const float* __restrict__ pev)
{
    extern __shared__ float xs[];            // 272*128 floats = 139,264 B

    const int nbg = blockIdx.x;              // 0..15
    const int bh  = blockIdx.y;              // b*2+h
    const int b   = bh >> 1, h = bh & 1;
    const int t   = blockIdx.z;              // 0=k, 1=v

    const float* x  = t ? vin : kin;
    const float* w  = t ? wv  : wk;
    const float* pe = t ? pev : pek;
    float* outp     = t ? g_vc : g_kc;

    const int tid  = threadIdx.x;
    const int dvec = tid & 31;               // float4 index over D
    const int ep   = tid >> 5;               // 0..15, 2 blks each

    const int nb0  = nbg * 16;
    const int JN   = (nbg == 15) ? 15 : 16;
    const int R    = JN * 16 + 16;
    const int row0 = nbg * 256;

    for (int i = tid; i < R * 128; i += 512) {
        int r = i >> 7, dd = i & 127;
        xs[i] = x[((b * SEQ + row0 + r) * HKV + h) * DIM + dd];
    }
    __syncthreads();

    ull acc[16][2];
#pragma unroll
    for (int j = 0; j < 16; ++j) { acc[j][0] = 0ull; acc[j][1] = 0ull; }
    ull pec0 = 0ull, pec1 = 0ull;

#pragma unroll
    for (int bq = 0; bq < 2; ++bq) {
        const int blk = ep * 2 + bq;
        const float* xb  = xs + blk * 128;               // + jj*2048 + dd
        const float* peb = pe + blk * 128;
        const ull*   wb  = (const ull*)w + (size_t)blk * 8192 + dvec * 2;
#pragma unroll 2
        for (int dd = 0; dd < 128; ++dd) {
            ulonglong2 w2 = *(const ulonglong2*)(wb + (size_t)dd * 64);
            float pv = peb[dd];
            ull pv2 = pack2(pv, pv);
            pec0 = ffma2(pv2, w2.x, pec0);
            pec1 = ffma2(pv2, w2.y, pec1);
#pragma unroll
            for (int jj = 0; jj < 16; ++jj) {
                float xv = xb[jj * 2048 + dd];           // broadcast LDS
                ull x2 = pack2(xv, xv);
                acc[jj][0] = ffma2(x2, w2.x, acc[jj][0]);
                acc[jj][1] = ffma2(x2, w2.y, acc[jj][1]);
            }
        }
    }

    // Single-pass 16-way reduction: red2[jj][tid] (131,072B) + pec (8,192B)
    __syncthreads();
    ulonglong2* red2  = (ulonglong2*)xs;          // 16*512 entries
    ulonglong2* red2p = red2 + 16 * 512;          // 512 entries

#pragma unroll
    for (int jj = 0; jj < 16; ++jj) {
        ulonglong2 v; v.x = acc[jj][0]; v.y = acc[jj][1];
        red2[jj * 512 + tid] = v;
    }
    {
        ulonglong2 v; v.x = pec0; v.y = pec1;
        red2p[tid] = v;
    }
    __syncthreads();

    {
        const int jj = tid >> 5;                  // 0..15
        const int dv = tid & 31;
        ull s0 = 0ull, s1 = 0ull;
#pragma unroll
        for (int e = 0; e < 16; ++e) {
            ulonglong2 a = red2[jj * 512 + e * 32 + dv];
            ulonglong2 p = red2p[e * 32 + dv];
            s0 = fadd2(s0, fadd2(a.x, p.x));
            s1 = fadd2(s1, fadd2(a.y, p.y));
        }
        int nb = nb0 + jj;
        if (nb < NBL) {
            float d0, d1, d2, d3;
            unpack2(s0, d0, d1);
            unpack2(s1, d2, d3);
            float4* o = (float4*)(outp + ((b * NBL + nb) * HKV + h) * DIM);
            o[dv] = make_float4(d0, d1, d2, d3);
        }
    }
}

// ---------------------------------------------------------------------------
// Attention kernel. grid (32 s-tiles, 16 g, 4 = b*2+h), block 512.
// LDS.128 everywhere: phase A does 2 kk per iter (Q dup-dup float4,
// K interleaved (c,c+32)x(kk,kk+1)); phase C does 4 mm per iter
// (Psm stride 260 for 16B alignment, Vt stride 36).
// Causal chunk skipping: pmax (64-col, phase A), mcmax (32-col, phase C).
// smem floats: Psm[128*260] @0 | Qsd4[128*17 f4] @33280 | Kp4[16*129 f4] @41984
//              Vt[128*36] @33280 (phase C, reuses Qsd4)
// ---------------------------------------------------------------------------
__global__ __launch_bounds__(512, 1)
void attn_kernel(const float* __restrict__ q, float* __restrict__ out,
                 float* __restrict__ attn, int write_attn)
{
    extern __shared__ float sm[];
    float*  Psm  = sm;                        // stride 260
    float2* Qsd2 = (float2*)(sm + 33280);     // [128][34] float2 (= [128][17] f4)
    float4* Qsd4 = (float4*)(sm + 33280);     // [128][17] float4
    float*  KpF  = sm + 41984;                // Kp4 as floats
    float4* Kp4  = (float4*)(sm + 41984);     // [16][129] float4
    float*  Vt   = sm + 33280;                // [128][36] (phase C)

    const int st = blockIdx.x;
    const int g  = blockIdx.y;
    const int bh = blockIdx.z;
    const int b  = bh >> 1, h = bh & 1;
    const int hq = h * GRP + g;
    const int s0 = st * 128;
    const int tid = threadIdx.x;
    const int rg  = tid >> 5;                 // 0..15
    const int cg  = tid & 31;                 // 0..31

    const int kvbase = (b * NBL * HKV + h) * DIM;

    const int NVC   = st * 8 + 7;                       // max valid col count
    const int pmax  = min(3, (NVC - 1) >> 6);           // live 64-col chunks
    const int mcmax = min(7, (NVC - 1) >> 5);           // live 32-col chunks

    // ---- Phase A: scores = Q (128xD) x Kc^T, col-paired f32x2, 2kk/iter ----
    ull acc[8][4];
#pragma unroll
    for (int i = 0; i < 8; ++i)
#pragma unroll
        for (int p = 0; p < 4; ++p) acc[i][p] = 0ull;

    const int kcols = (pmax + 1) * 64;        // K columns actually staged

    for (int c4 = 0; c4 < 4; ++c4) {
        const int kc0 = c4 * 32;
        for (int i = tid; i < 128 * 32; i += 512) {
            int r = i >> 5, kk = i & 31;
            float qv = q[((size_t)((b * SEQ + s0 + r) * HQN + hq)) * DIM + kc0 + kk];
            Qsd2[r * 34 + kk] = make_float2(qv, qv);
        }
        for (int i = tid; i < kcols * 32; i += 512) {
            int c = i >> 5, kk = i & 31;
            float kvv = (c < NBL) ? g_kc[kvbase + c * (HKV * DIM) + kc0 + kk] : 0.f;
            int pc = (c & 31) + 32 * (c >> 6);
            int fi = (kk >> 1) * 516 + pc * 4 + ((kk & 1) << 1) + ((c >> 5) & 1);
            KpF[fi] = kvv;
        }
        __syncthreads();
#pragma unroll 4
        for (int kkp = 0; kkp < 16; ++kkp) {
            ulonglong2 a2[8];
#pragma unroll
            for (int i = 0; i < 8; ++i)
                a2[i] = *(const ulonglong2*)(Qsd4 + (rg + 16 * i) * 17 + kkp); // bcast 16B
#pragma unroll
            for (int p = 0; p < 4; ++p) {
                if (p <= pmax) {
                    ulonglong2 b2 = *(const ulonglong2*)(Kp4 + kkp * 129 + p * 32 + cg);
#pragma unroll
                    for (int i = 0; i < 8; ++i) {
                        acc[i][p] = ffma2(a2[i].x, b2.x, acc[i][p]);
                        acc[i][p] = ffma2(a2[i].y, b2.y, acc[i][p]);
                    }
                }
            }
        }
        __syncthreads();
    }

    // ---- Softmax in registers (warp-shuffle row reductions) ----
    const size_t abase = (((size_t)b * HQN + hq) * SEQ + s0) * NBL;
#pragma unroll
    for (int i = 0; i < 8; ++i) {
        const int r = rg + 16 * i;
        const int s = s0 + r;
        const int nv = (s >= 31) ? (((s - 31) >> 4) + 1) : 0;
        float v[8];
#pragma unroll
        for (int p = 0; p < 4; ++p) {
            float lo, hi; unpack2(acc[i][p], lo, hi);
            v[2 * p]     = lo * SCALE;    // col cg+64p
            v[2 * p + 1] = hi * SCALE;    // col cg+64p+32
        }
        float m = -1e30f;
#pragma unroll
        for (int p = 0; p < 4; ++p) {
            int c0 = cg + 64 * p;
            if (c0 < nv)      m = fmaxf(m, v[2 * p]);
            if (c0 + 32 < nv) m = fmaxf(m, v[2 * p + 1]);
        }
#pragma unroll
        for (int off = 16; off >= 1; off >>= 1)
            m = fmaxf(m, __shfl_xor_sync(0xffffffffu, m, off));
        float ssum = 0.f;
#pragma unroll
        for (int p = 0; p < 4; ++p) {
            int c0 = cg + 64 * p;
            float e0 = (c0 < nv)      ? __expf(v[2 * p] - m)     : 0.f;
            float e1 = (c0 + 32 < nv) ? __expf(v[2 * p + 1] - m) : 0.f;
            v[2 * p] = e0; v[2 * p + 1] = e1;
            ssum += e0 + e1;
        }
#pragma unroll
        for (int off = 16; off >= 1; off >>= 1)
            ssum += __shfl_xor_sync(0xffffffffu, ssum, off);
        const float inv = 1.f / fmaxf(ssum, 1e-20f);
        float* prow = Psm + r * 260;
#pragma unroll
        for (int p = 0; p < 4; ++p) {
            int c0 = cg + 64 * p, c1 = c0 + 32;
            float p0 = v[2 * p] * inv, p1 = v[2 * p + 1] * inv;
            prow[c0] = p0;
            prow[c1] = p1;
            if (write_attn) {
                attn[abase + (size_t)r * NBL + c0] = p0;            // c0 <= 223
                if (c1 < NBL) attn[abase + (size_t)r * NBL + c1] = p1;
            }
        }
    }
    __syncthreads();

    // ---- Phase C: out = P (128x255) x Vc (255x128), 4 mm per iter ----
    ull oacc[8][4];
#pragma unroll
    for (int i = 0; i < 8; ++i)
#pragma unroll
        for (int j = 0; j < 4; ++j) oacc[i][j] = 0ull;

    for (int mc = 0; mc <= mcmax; ++mc) {
        __syncthreads();
        for (int i = tid; i < 32 * 128; i += 512) {
            int mm = i >> 7, dd = i & 127;
            int nb = mc * 32 + mm;
            Vt[dd * 36 + mm] = (nb < NBL) ? g_vc[kvbase + nb * (HKV * DIM) + dd] : 0.f;
        }
        __syncthreads();
#pragma unroll 2
        for (int m4 = 0; m4 < 8; ++m4) {
            ulonglong2 a2[8];
#pragma unroll
            for (int i = 0; i < 8; ++i)
                a2[i] = *(const ulonglong2*)(Psm + (rg + 16 * i) * 260 + mc * 32 + 4 * m4);
#pragma unroll
            for (int j = 0; j < 4; ++j) {
                ulonglong2 b2 = *(const ulonglong2*)(Vt + (cg + 32 * j) * 36 + 4 * m4);
#pragma unroll
                for (int i = 0; i < 8; ++i) {
                    oacc[i][j] = ffma2(a2[i].x, b2.x, oacc[i][j]);
                    oacc[i][j] = ffma2(a2[i].y, b2.y, oacc[i][j]);
                }
            }
        }
    }

    // ---- Store out: (BS, S, HQ, D) ----
#pragma unroll
    for (int i = 0; i < 8; ++i) {
        int s = s0 + rg + 16 * i;
        size_t obase = ((size_t)(b * SEQ + s) * HQN + hq) * DIM;
#pragma unroll
        for (int j = 0; j < 4; ++j) {
            float lo, hi; unpack2(oacc[i][j], lo, hi);
            out[obase + cg + 32 * j] = lo + hi;
        }
    }
}

// ---------------------------------------------------------------------------
extern "C" void kernel_launch(void* const* d_in, const int* in_sizes, int n_in,
                              void* d_out, int out_size)
{
    const float* q   = (const float*)d_in[0];
    const float* k   = (const float*)d_in[1];
    const float* v   = (const float*)d_in[2];
    // d_in[3] = cu_seqlens_k (fixed [0,S,2S]) — unused
    const float* wk  = (const float*)d_in[4];
    const float* wv  = (const float*)d_in[5];
    const float* pek = (const float*)d_in[6];
    const float* pev = (const float*)d_in[7];

    float* out  = (float*)d_out;
    float* attn = out + OUT_ELEMS;
    int write_attn = ((size_t)out_size >= OUT_ELEMS + ATTN_ELEMS) ? 1 : 0;

    const int COMP_SMEM = 272 * 128 * 4;                         // 139,264 B
    const int ATT_SMEM  = (33280 + 8704 + 8256) * 4;             // 200,960 B

    cudaFuncSetAttribute(compress_kernel,
                         cudaFuncAttributeMaxDynamicSharedMemorySize, COMP_SMEM);
    cudaFuncSetAttribute(attn_kernel,
                         cudaFuncAttributeMaxDynamicSharedMemorySize, ATT_SMEM);

    compress_kernel<<<dim3(16, 4, 2), 512, COMP_SMEM>>>(k, v, wk, wv, pek, pev);
    attn_kernel<<<dim3(32, 16, 4), 512, ATT_SMEM>>>(q, out, attn, write_attn);
}

// round 9
// speedup vs baseline: 2.5285x; 1.3863x over previous
#include <cuda_runtime.h>
#include <cuda_bf16.h>

// Problem constants (fixed by reference setup)
#define BSZ     2
#define SEQ     4096
#define HQN     32
#define HKV     2
#define DIM     128
#define NBL     255
#define GRP     16
#define SCALE   0.08838834764831845f   // 1/sqrt(128)

#define OUT_ELEMS  ((size_t)BSZ*SEQ*HQN*DIM)            // 33,554,432
#define ATTN_ELEMS ((size_t)BSZ*HQN*SEQ*NBL)            // 66,846,720

typedef unsigned long long ull;
typedef unsigned int       u32;

// Compressed K/V in bf16 hi/lo split. nb padded to 256; index 255 stays zero
// (device globals are zero-initialized; row 255 is never written).
// K: [bh][nb(256)][d(128)]   V (pre-transposed): [bh][d(128)][nb(256)]
__device__ __nv_bfloat16 g_kh [4*256*128];
__device__ __nv_bfloat16 g_kl [4*256*128];
__device__ __nv_bfloat16 g_vth[4*128*256];
__device__ __nv_bfloat16 g_vtl[4*128*256];

// ---- packed f32x2 helpers (compress kernel) -------------------------------
__device__ __forceinline__ ull pack2(float lo, float hi) {
    ull r; asm("mov.b64 %0,{%1,%2};" : "=l"(r) : "f"(lo), "f"(hi)); return r;
}
__device__ __forceinline__ void unpack2(ull v, float& lo, float& hi) {
    asm("mov.b64 {%0,%1},%2;" : "=f"(lo), "=f"(hi) : "l"(v));
}
__device__ __forceinline__ ull ffma2(ull a, ull b, ull c) {
    ull d; asm("fma.rn.f32x2 %0,%1,%2,%3;" : "=l"(d) : "l"(a), "l"(b), "l"(c)); return d;
}
__device__ __forceinline__ ull fadd2(ull a, ull b) {
    ull d; asm("add.rn.f32x2 %0,%1,%2;" : "=l"(d) : "l"(a), "l"(b)); return d;
}

// ---- warp-MMA helpers (sm_80-class, valid on non-'a' target) --------------
__device__ __forceinline__ u32 smem_u32(const void* p) {
    u32 a; asm("{ .reg .u64 t; cvta.to.shared.u64 t, %1; cvt.u32.u64 %0, t; }"
               : "=r"(a) : "l"(p));
    return a;
}
__device__ __forceinline__ void ldsm4(u32* r, u32 addr) {
    asm volatile("ldmatrix.sync.aligned.m8n8.x4.shared.b16 {%0,%1,%2,%3}, [%4];"
        : "=r"(r[0]), "=r"(r[1]), "=r"(r[2]), "=r"(r[3]) : "r"(addr));
}
__device__ __forceinline__ void mma16816(float* d, const u32* a, u32 b0, u32 b1) {
    asm volatile("mma.sync.aligned.m16n8k16.row.col.f32.bf16.bf16.f32 "
        "{%0,%1,%2,%3},{%4,%5,%6,%7},{%8,%9},{%0,%1,%2,%3};"
        : "+f"(d[0]), "+f"(d[1]), "+f"(d[2]), "+f"(d[3])
        : "r"(a[0]), "r"(a[1]), "r"(a[2]), "r"(a[3]), "r"(b0), "r"(b1));
}
__device__ __forceinline__ u32 pkbf(__nv_bfloat16 a, __nv_bfloat16 b) {
    __nv_bfloat162 t(a, b);                 // .x at low halfword
    return *(u32*)&t;
}

// ---------------------------------------------------------------------------
// Compression kernel. grid (16, 4, 2), block 512 (R5 structure, ~82us).
// Outputs bf16 hi/lo; V pre-transposed to [bh][d][nb].
// ---------------------------------------------------------------------------
__global__ __launch_bounds__(512, 1)
void compress_kernel(const float* __restrict__ kin, const float* __restrict__ vin,
                     const float* __restrict__ wk,  const float* __restrict__ wv,
                     const float* __restrict__ pek, const float* __restrict__ pev)
{
    extern __shared__ float xs[];            // 272*128 floats = 139,264 B

    const int nbg = blockIdx.x;
    const int bh  = blockIdx.y;              // b*2+h
    const int b   = bh >> 1, h = bh & 1;
    const int t   = blockIdx.z;              // 0=k, 1=v

    const float* x  = t ? vin : kin;
    const float* w  = t ? wv  : wk;
    const float* pe = t ? pev : pek;

    const int tid  = threadIdx.x;
    const int dvec = tid & 31;
    const int ep   = tid >> 5;               // 0..15, 2 blks each

    const int nb0  = nbg * 16;
    const int JN   = (nbg == 15) ? 15 : 16;
    const int R    = JN * 16 + 16;
    const int row0 = nbg * 256;

    for (int i = tid; i < R * 128; i += 512) {
        int r = i >> 7, dd = i & 127;
        xs[i] = x[((b * SEQ + row0 + r) * HKV + h) * DIM + dd];
    }
    __syncthreads();

    ull acc[16][2];
#pragma unroll
    for (int j = 0; j < 16; ++j) { acc[j][0] = 0ull; acc[j][1] = 0ull; }
    ull pec0 = 0ull, pec1 = 0ull;

#pragma unroll
    for (int bq = 0; bq < 2; ++bq) {
        const int blk = ep * 2 + bq;
        const float* xb  = xs + blk * 128;
        const float* peb = pe + blk * 128;
        const ull*   wb  = (const ull*)w + (size_t)blk * 8192 + dvec * 2;
#pragma unroll 2
        for (int dd = 0; dd < 128; ++dd) {
            ulonglong2 w2 = *(const ulonglong2*)(wb + (size_t)dd * 64);
            float pv = peb[dd];
            ull pv2 = pack2(pv, pv);
            pec0 = ffma2(pv2, w2.x, pec0);
            pec1 = ffma2(pv2, w2.y, pec1);
#pragma unroll
            for (int jj = 0; jj < 16; ++jj) {
                float xv = xb[jj * 2048 + dd];
                ull x2 = pack2(xv, xv);
                acc[jj][0] = ffma2(x2, w2.x, acc[jj][0]);
                acc[jj][1] = ffma2(x2, w2.y, acc[jj][1]);
            }
        }
    }

    __syncthreads();
    ulonglong2* red2  = (ulonglong2*)xs;
    ulonglong2* red2p = red2 + 16 * 512;

#pragma unroll
    for (int jj = 0; jj < 16; ++jj) {
        ulonglong2 v; v.x = acc[jj][0]; v.y = acc[jj][1];
        red2[jj * 512 + tid] = v;
    }
    { ulonglong2 v; v.x = pec0; v.y = pec1; red2p[tid] = v; }
    __syncthreads();

    {
        const int jj = tid >> 5;
        const int dv = tid & 31;
        ull s0 = 0ull, s1 = 0ull;
#pragma unroll
        for (int e = 0; e < 16; ++e) {
            ulonglong2 a = red2[jj * 512 + e * 32 + dv];
            ulonglong2 p = red2p[e * 32 + dv];
            s0 = fadd2(s0, fadd2(a.x, p.x));
            s1 = fadd2(s1, fadd2(a.y, p.y));
        }
        int nb = nb0 + jj;
        if (nb < NBL) {
            float d0, d1, d2, d3;
            unpack2(s0, d0, d1);
            unpack2(s1, d2, d3);
            float dd[4] = {d0, d1, d2, d3};
            __nv_bfloat16 hh[4], ll[4];
#pragma unroll
            for (int i = 0; i < 4; ++i) {
                hh[i] = __float2bfloat16(dd[i]);
                ll[i] = __float2bfloat16(dd[i] - __bfloat162float(hh[i]));
            }
            if (t == 0) {   // K: [bh][nb][d]
                u32* dh = (u32*)(g_kh + ((bh * 256 + nb) * 128 + dv * 4));
                u32* dl = (u32*)(g_kl + ((bh * 256 + nb) * 128 + dv * 4));
                dh[0] = pkbf(hh[0], hh[1]); dh[1] = pkbf(hh[2], hh[3]);
                dl[0] = pkbf(ll[0], ll[1]); dl[1] = pkbf(ll[2], ll[3]);
            } else {        // V transposed: [bh][d][nb]
#pragma unroll
                for (int i = 0; i < 4; ++i) {
                    size_t o = (size_t)(bh * 128 + dv * 4 + i) * 256 + nb;
                    g_vth[o] = hh[i];
                    g_vtl[o] = ll[i];
                }
            }
        }
    }
}

// ---------------------------------------------------------------------------
// Attention kernel — warp-level bf16 MMA, 3-pass hi/lo split.
// grid (32, 16, 4), block 512 (16 warps = 4 row-groups x 4 col-groups).
// Phase A: warp (r4,c4) -> rows r4*32..+31, score cols c4*64..+63.
// Softmax in registers (quad shuffles + smem cross-c4 reduce).
// P restored to smem bf16 hi/lo (reuses K region); phase C: warp covers
// rows r4*32, out d-cols c4*32, k = full valid nb range (no reduction).
// XOR swizzle: 16B chunk c at row r stored at chunk (c ^ (r&7)).
// SMEM bytes: rmax@0(2K) rsum@2048(2K) | QH@4096 QL@36864 (32K each)
//             KH@69632 KL@135168 (64K each)  [phase C: PH=KH PL=KL,
//             VH@4096 VL@20480 (16K each, reuse Q)]   total 200,704
// NOTE: attn stores are SCALAR (NBL=255 odd -> row bases only 4B-aligned;
// an STG.64 there traps with misaligned address — seen in R7).
// ---------------------------------------------------------------------------
#define SM_RMAX  0
#define SM_RSUM  2048
#define SM_QH    4096
#define SM_QL    36864
#define SM_KH    69632
#define SM_KL    135168
#define SM_VH    SM_QH
#define SM_VL    (SM_QH + 16384)
#define SM_PH    SM_KH
#define SM_PL    SM_KL
#define ATT_SMEM 200704

__global__ __launch_bounds__(512, 1)
void attn_kernel(const float* __restrict__ q, float* __restrict__ out,
                 float* __restrict__ attn, int write_attn)
{
    extern __shared__ char smc[];
    const u32 sb = smem_u32(smc);
    float* rmax = (float*)(smc + SM_RMAX);   // [4 c4][128 rows]
    float* rsum = (float*)(smc + SM_RSUM);

    const int st = blockIdx.x;
    const int g  = blockIdx.y;
    const int bh = blockIdx.z;
    const int b  = bh >> 1, h = bh & 1;
    const int hq = h * GRP + g;
    const int s0 = st * 128;
    const int tid  = threadIdx.x;
    const int w    = tid >> 5;
    const int lane = tid & 31;
    const int r4 = w >> 2, c4 = w & 3;
    const int gq = lane >> 2, tq = lane & 3; // mma quad coords
    const int li = lane & 15, lh = lane >> 4;

    const int NVC   = st * 8 + 7;            // max valid col count in CTA
    const int NA    = (st < 16) ? 128 : 256; // staged K rows
    const int rbase = r4 * 32;
    const int cbase = c4 * 64;

    // ---- Stage Q (f32 -> bf16 hi/lo), swizzled [128][128] stride 256B ----
    for (int u = tid; u < 8192; u += 512) {
        int r = u >> 6, k2 = u & 63;
        float2 qv = *(const float2*)(q + ((size_t)((b * SEQ + s0 + r) * HQN + hq)) * DIM + k2 * 2);
        __nv_bfloat16 h0 = __float2bfloat16(qv.x);
        __nv_bfloat16 h1 = __float2bfloat16(qv.y);
        __nv_bfloat16 l0 = __float2bfloat16(qv.x - __bfloat162float(h0));
        __nv_bfloat16 l1 = __float2bfloat16(qv.y - __bfloat162float(h1));
        u32 off = (u32)r * 256 + (((((u32)k2) >> 2) ^ (r & 7)) << 4) + (k2 & 3) * 4;
        *(u32*)(smc + SM_QH + off) = pkbf(h0, h1);
        *(u32*)(smc + SM_QL + off) = pkbf(l0, l1);
    }
    // ---- Stage K hi/lo, swizzled [NA][128] stride 256B ----
    {
        const u32* kh = (const u32*)g_kh + (size_t)bh * 16384;
        const u32* kl = (const u32*)g_kl + (size_t)bh * 16384;
        for (int u = tid; u < NA * 64; u += 512) {
            int nb = u >> 6, k2 = u & 63;
            u32 off = (u32)nb * 256 + (((((u32)k2) >> 2) ^ (nb & 7)) << 4) + (k2 & 3) * 4;
            *(u32*)(smc + SM_KH + off) = kh[nb * 64 + k2];
            *(u32*)(smc + SM_KL + off) = kl[nb * 64 + k2];
        }
    }
    __syncthreads();

    // ---- Phase A: D[16][4] frags; tile ti = stripe*8 + j (j: 8-col tile) --
    float D[16][4];
#pragma unroll
    for (int i = 0; i < 16; ++i) { D[i][0] = D[i][1] = D[i][2] = D[i][3] = 0.f; }

    int jlim = (NVC - cbase + 7) >> 3;
    jlim = (jlim < 0) ? 0 : ((jlim > 8) ? 8 : jlim);
    const int plim = (jlim + 1) >> 1;        // n-tile pairs (16 cols each)

    for (int ks = 0; ks < 8; ++ks) {
        u32 ah[2][4], al[2][4];
#pragma unroll
        for (int sp = 0; sp < 2; ++sp) {
            int ri = rbase + sp * 16 + li;
            u32 ci = (u32)(ks * 2 + lh);
            u32 off = (u32)ri * 256 + ((ci ^ (ri & 7)) << 4);
            ldsm4(ah[sp], sb + SM_QH + off);
            ldsm4(al[sp], sb + SM_QL + off);
        }
        for (int jp = 0; jp < plim; ++jp) {
            int ri = cbase + jp * 16 + li;
            u32 ci = (u32)(ks * 2 + lh);
            u32 off = (u32)ri * 256 + ((ci ^ (ri & 7)) << 4);
            u32 bh4[4], bl4[4];
            ldsm4(bh4, sb + SM_KH + off);
            ldsm4(bl4, sb + SM_KL + off);
#pragma unroll
            for (int sp = 0; sp < 2; ++sp) {
                float* d0 = D[sp * 8 + 2 * jp];
                float* d1 = D[sp * 8 + 2 * jp + 1];
                mma16816(d0, ah[sp], bh4[0], bh4[2]);
                mma16816(d0, al[sp], bh4[0], bh4[2]);
                mma16816(d0, ah[sp], bl4[0], bl4[2]);
                mma16816(d1, ah[sp], bh4[1], bh4[3]);
                mma16816(d1, al[sp], bh4[1], bh4[3]);
                mma16816(d1, ah[sp], bl4[1], bl4[3]);
            }
        }
    }

    // ---- Softmax in registers. Thread rows: rbase+sp*16+gq+hf*8 ----
#pragma unroll
    for (int slot = 0; slot < 4; ++slot) {
        int sp = slot >> 1, hf = slot & 1;
        int row = rbase + sp * 16 + gq + hf * 8;
        int s = s0 + row;
        int nv = (s >= 31) ? (((s - 31) >> 4) + 1) : 0;
        float mloc = -1e30f;
#pragma unroll
        for (int j = 0; j < 8; ++j) {
            int c0 = cbase + j * 8 + 2 * tq;
            if (c0     < nv) mloc = fmaxf(mloc, D[sp * 8 + j][hf * 2]     * SCALE);
            if (c0 + 1 < nv) mloc = fmaxf(mloc, D[sp * 8 + j][hf * 2 + 1] * SCALE);
        }
        mloc = fmaxf(mloc, __shfl_xor_sync(0xffffffffu, mloc, 1));
        mloc = fmaxf(mloc, __shfl_xor_sync(0xffffffffu, mloc, 2));
        if (tq == 0) rmax[c4 * 128 + row] = mloc;
    }
    __syncthreads();
#pragma unroll
    for (int slot = 0; slot < 4; ++slot) {
        int sp = slot >> 1, hf = slot & 1;
        int row = rbase + sp * 16 + gq + hf * 8;
        int s = s0 + row;
        int nv = (s >= 31) ? (((s - 31) >> 4) + 1) : 0;
        float m = fmaxf(fmaxf(rmax[row], rmax[128 + row]),
                        fmaxf(rmax[256 + row], rmax[384 + row]));
        float sl = 0.f;
#pragma unroll
        for (int j = 0; j < 8; ++j) {
            int c0 = cbase + j * 8 + 2 * tq;
            float e0 = (c0     < nv) ? __expf(D[sp * 8 + j][hf * 2]     * SCALE - m) : 0.f;
            float e1 = (c0 + 1 < nv) ? __expf(D[sp * 8 + j][hf * 2 + 1] * SCALE - m) : 0.f;
            D[sp * 8 + j][hf * 2]     = e0;
            D[sp * 8 + j][hf * 2 + 1] = e1;
            sl += e0 + e1;
        }
        sl += __shfl_xor_sync(0xffffffffu, sl, 1);
        sl += __shfl_xor_sync(0xffffffffu, sl, 2);
        if (tq == 0) rsum[c4 * 128 + row] = sl;
    }
    __syncthreads();
    // normalize + attn write (scalar stores!) + P -> smem bf16 hi/lo
    // (reuses K region; safe: all K reads finished before rmax barrier)
#pragma unroll
    for (int slot = 0; slot < 4; ++slot) {
        int sp = slot >> 1, hf = slot & 1;
        int row = rbase + sp * 16 + gq + hf * 8;
        float tot = rsum[row] + rsum[128 + row] + rsum[256 + row] + rsum[384 + row];
        float inv = 1.f / fmaxf(tot, 1e-20f);
        size_t arow = (((size_t)b * HQN + hq) * SEQ + s0 + row) * NBL;
#pragma unroll
        for (int j = 0; j < 8; ++j) {
            int c0 = cbase + j * 8 + 2 * tq;
            float p0 = D[sp * 8 + j][hf * 2]     * inv;
            float p1 = D[sp * 8 + j][hf * 2 + 1] * inv;
            if (write_attn) {
                attn[arow + c0] = p0;                 // c0 <= 254 always
                if (c0 + 1 < NBL) attn[arow + c0 + 1] = p1;
            }
            __nv_bfloat16 h0 = __float2bfloat16(p0);
            __nv_bfloat16 h1 = __float2bfloat16(p1);
            __nv_bfloat16 l0 = __float2bfloat16(p0 - __bfloat162float(h0));
            __nv_bfloat16 l1 = __float2bfloat16(p1 - __bfloat162float(h1));
            u32 ch = (u32)(((cbase >> 3) + j) ^ (row & 7));
            u32 off = (u32)row * 512 + (ch << 4) + tq * 4;
            *(u32*)(smc + SM_PH + off) = pkbf(h0, h1);
            *(u32*)(smc + SM_PL + off) = pkbf(l0, l1);
        }
    }
    __syncthreads();

    // ---- Phase C: out rows rbase..+31, d cols c4*32..+31; k over valid nb --
    const int KSC = min((NVC + 15) >> 4, NA >> 4);   // valid k16 steps
    const int dbase = c4 * 32;
    float C[8][4];                                    // ti = sp*4 + dt
#pragma unroll
    for (int i = 0; i < 8; ++i) { C[i][0] = C[i][1] = C[i][2] = C[i][3] = 0.f; }

    const u32* vh = (const u32*)g_vth + (size_t)bh * 16384;
    const u32* vl = (const u32*)g_vtl + (size_t)bh * 16384;
    const int nchunks = (KSC + 3) >> 2;               // 64-nb chunks
    for (int kc = 0; kc < nchunks; ++kc) {
        // stage V chunk [128 d][64 nb] hi/lo, stride 128B, swizzled
        for (int u = tid; u < 4096; u += 512) {
            int dd = u >> 5, n2 = u & 31;
            u32 off = (u32)dd * 128 + (((((u32)n2) >> 2) ^ (dd & 7)) << 4) + (n2 & 3) * 4;
            *(u32*)(smc + SM_VH + off) = vh[dd * 128 + kc * 32 + n2];
            *(u32*)(smc + SM_VL + off) = vl[dd * 128 + kc * 32 + n2];
        }
        __syncthreads();
        const int kshi = min(kc * 4 + 4, KSC);
        for (int ks = kc * 4; ks < kshi; ++ks) {
            u32 ph4[2][4], pl4[2][4];
#pragma unroll
            for (int sp = 0; sp < 2; ++sp) {
                int ri = rbase + sp * 16 + li;
                u32 ci = (u32)(ks * 2 + lh);
                u32 off = (u32)ri * 512 + ((ci ^ (ri & 7)) << 4);
                ldsm4(ph4[sp], sb + SM_PH + off);
                ldsm4(pl4[sp], sb + SM_PL + off);
            }
            const int ks4 = ks - kc * 4;
#pragma unroll
            for (int dp = 0; dp < 2; ++dp) {
                int ri = dbase + dp * 16 + li;
                u32 ci = (u32)(ks4 * 2 + lh);
                u32 off = (u32)ri * 128 + ((ci ^ (ri & 7)) << 4);
                u32 bh4[4], bl4[4];
                ldsm4(bh4, sb + SM_VH + off);
                ldsm4(bl4, sb + SM_VL + off);
#pragma unroll
                for (int sp = 0; sp < 2; ++sp) {
                    float* c0 = C[sp * 4 + 2 * dp];
                    float* c1 = C[sp * 4 + 2 * dp + 1];
                    mma16816(c0, ph4[sp], bh4[0], bh4[2]);
                    mma16816(c0, pl4[sp], bh4[0], bh4[2]);
                    mma16816(c0, ph4[sp], bl4[0], bl4[2]);
                    mma16816(c1, ph4[sp], bh4[1], bh4[3]);
                    mma16816(c1, pl4[sp], bh4[1], bh4[3]);
                    mma16816(c1, ph4[sp], bl4[1], bl4[3]);
                }
            }
        }
        __syncthreads();
    }

    // ---- Store out: (BS, S, HQ, D), float2 per fragment pair ----
#pragma unroll
    for (int slot = 0; slot < 4; ++slot) {
        int sp = slot >> 1, hf = slot & 1;
        int row = rbase + sp * 16 + gq + hf * 8;
        float* op = out + ((size_t)(b * SEQ + s0 + row) * HQN + hq) * DIM + dbase;
#pragma unroll
        for (int dt = 0; dt < 4; ++dt) {
            *(float2*)(op + dt * 8 + 2 * tq) =
                make_float2(C[sp * 4 + dt][hf * 2], C[sp * 4 + dt][hf * 2 + 1]);
        }
    }
}

// ---------------------------------------------------------------------------
extern "C" void kernel_launch(void* const* d_in, const int* in_sizes, int n_in,
                              void* d_out, int out_size)
{
    const float* q   = (const float*)d_in[0];
    const float* k   = (const float*)d_in[1];
    const float* v   = (const float*)d_in[2];
    // d_in[3] = cu_seqlens_k (fixed [0,S,2S]) — unused
    const float* wk  = (const float*)d_in[4];
    const float* wv  = (const float*)d_in[5];
    const float* pek = (const float*)d_in[6];
    const float* pev = (const float*)d_in[7];

    float* out  = (float*)d_out;
    float* attn = out + OUT_ELEMS;
    int write_attn = ((size_t)out_size >= OUT_ELEMS + ATTN_ELEMS) ? 1 : 0;

    const int COMP_SMEM = 272 * 128 * 4;                 // 139,264 B

    cudaFuncSetAttribute(compress_kernel,
                         cudaFuncAttributeMaxDynamicSharedMemorySize, COMP_SMEM);
    cudaFuncSetAttribute(attn_kernel,
                         cudaFuncAttributeMaxDynamicSharedMemorySize, ATT_SMEM);

    compress_kernel<<<dim3(16, 4, 2), 512, COMP_SMEM>>>(k, v, wk, wv, pek, pev);
    attn_kernel<<<dim3(32, 16, 4), 512, ATT_SMEM>>>(q, out, attn, write_attn);
}

// round 10
// speedup vs baseline: 3.9625x; 1.5671x over previous
#include <cuda_runtime.h>
#include <cuda_fp16.h>

// Problem constants (fixed by reference setup)
#define BSZ     2
#define SEQ     4096
#define HQN     32
#define HKV     2
#define DIM     128
#define NBL     255
#define GRP     16
#define SCALE   0.08838834764831845f   // 1/sqrt(128)

#define OUT_ELEMS  ((size_t)BSZ*SEQ*HQN*DIM)            // 33,554,432
#define ATTN_ELEMS ((size_t)BSZ*HQN*SEQ*NBL)            // 66,846,720

typedef unsigned long long ull;
typedef unsigned int       u32;

// Compressed K/V in fp16. nb padded to 256; index 255 stays zero
// (device globals are zero-initialized; row 255 is never written).
// K: [bh][nb(256)][d(128)]   V (pre-transposed): [bh][d(128)][nb(256)]
__device__ __half g_k16 [4*256*128];
__device__ __half g_vt16[4*128*256];

// ---- packed f32x2 helpers (compress kernel) -------------------------------
__device__ __forceinline__ ull pack2(float lo, float hi) {
    ull r; asm("mov.b64 %0,{%1,%2};" : "=l"(r) : "f"(lo), "f"(hi)); return r;
}
__device__ __forceinline__ void unpack2(ull v, float& lo, float& hi) {
    asm("mov.b64 {%0,%1},%2;" : "=f"(lo), "=f"(hi) : "l"(v));
}
__device__ __forceinline__ ull ffma2(ull a, ull b, ull c) {
    ull d; asm("fma.rn.f32x2 %0,%1,%2,%3;" : "=l"(d) : "l"(a), "l"(b), "l"(c)); return d;
}
__device__ __forceinline__ ull fadd2(ull a, ull b) {
    ull d; asm("add.rn.f32x2 %0,%1,%2;" : "=l"(d) : "l"(a), "l"(b)); return d;
}

// ---- warp-MMA helpers (sm_80-class, valid on non-'a' target) --------------
__device__ __forceinline__ u32 smem_u32(const void* p) {
    u32 a; asm("{ .reg .u64 t; cvta.to.shared.u64 t, %1; cvt.u32.u64 %0, t; }"
               : "=r"(a) : "l"(p));
    return a;
}
__device__ __forceinline__ void ldsm4(u32* r, u32 addr) {
    asm volatile("ldmatrix.sync.aligned.m8n8.x4.shared.b16 {%0,%1,%2,%3}, [%4];"
        : "=r"(r[0]), "=r"(r[1]), "=r"(r[2]), "=r"(r[3]) : "r"(addr));
}
__device__ __forceinline__ void mma16816(float* d, const u32* a, u32 b0, u32 b1) {
    asm volatile("mma.sync.aligned.m16n8k16.row.col.f32.f16.f16.f32 "
        "{%0,%1,%2,%3},{%4,%5,%6,%7},{%8,%9},{%0,%1,%2,%3};"
        : "+f"(d[0]), "+f"(d[1]), "+f"(d[2]), "+f"(d[3])
        : "r"(a[0]), "r"(a[1]), "r"(a[2]), "r"(a[3]), "r"(b0), "r"(b1));
}
__device__ __forceinline__ u32 pkhf(__half a, __half b) {
    __half2 t(a, b);                        // .x at low halfword
    return *(u32*)&t;
}
#define CP_A16(dst, src) \
    asm volatile("cp.async.cg.shared.global [%0], [%1], 16;" \
                 :: "r"(dst), "l"(src) : "memory")
#define CP_COMMIT()  asm volatile("cp.async.commit_group;" ::: "memory")
#define CP_WAIT(N)   asm volatile("cp.async.wait_group %0;" :: "n"(N) : "memory")

// ---------------------------------------------------------------------------
// Compression kernel. grid (16, 4, 2), block 512 (R5 structure).
// Outputs fp16 (single precision level); V pre-transposed to [bh][d][nb].
// ---------------------------------------------------------------------------
__global__ __launch_bounds__(512, 1)
void compress_kernel(const float* __restrict__ kin, const float* __restrict__ vin,
                     const float* __restrict__ wk,  const float* __restrict__ wv,
                     const float* __restrict__ pek, const float* __restrict__ pev)
{
    extern __shared__ float xs[];            // 272*128 floats = 139,264 B

    const int nbg = blockIdx.x;
    const int bh  = blockIdx.y;              // b*2+h
    const int b   = bh >> 1, h = bh & 1;
    const int t   = blockIdx.z;              // 0=k, 1=v

    const float* x  = t ? vin : kin;
    const float* w  = t ? wv  : wk;
    const float* pe = t ? pev : pek;

    const int tid  = threadIdx.x;
    const int dvec = tid & 31;
    const int ep   = tid >> 5;               // 0..15, 2 blks each

    const int nb0  = nbg * 16;
    const int JN   = (nbg == 15) ? 15 : 16;
    const int R    = JN * 16 + 16;
    const int row0 = nbg * 256;

    for (int i = tid; i < R * 128; i += 512) {
        int r = i >> 7, dd = i & 127;
        xs[i] = x[((b * SEQ + row0 + r) * HKV + h) * DIM + dd];
    }
    __syncthreads();

    ull acc[16][2];
#pragma unroll
    for (int j = 0; j < 16; ++j) { acc[j][0] = 0ull; acc[j][1] = 0ull; }
    ull pec0 = 0ull, pec1 = 0ull;

#pragma unroll
    for (int bq = 0; bq < 2; ++bq) {
        const int blk = ep * 2 + bq;
        const float* xb  = xs + blk * 128;
        const float* peb = pe + blk * 128;
        const ull*   wb  = (const ull*)w + (size_t)blk * 8192 + dvec * 2;
#pragma unroll 2
        for (int dd = 0; dd < 128; ++dd) {
            ulonglong2 w2 = *(const ulonglong2*)(wb + (size_t)dd * 64);
            float pv = peb[dd];
            ull pv2 = pack2(pv, pv);
            pec0 = ffma2(pv2, w2.x, pec0);
            pec1 = ffma2(pv2, w2.y, pec1);
#pragma unroll
            for (int jj = 0; jj < 16; ++jj) {
                float xv = xb[jj * 2048 + dd];
                ull x2 = pack2(xv, xv);
                acc[jj][0] = ffma2(x2, w2.x, acc[jj][0]);
                acc[jj][1] = ffma2(x2, w2.y, acc[jj][1]);
            }
        }
    }

    __syncthreads();
    ulonglong2* red2  = (ulonglong2*)xs;
    ulonglong2* red2p = red2 + 16 * 512;

#pragma unroll
    for (int jj = 0; jj < 16; ++jj) {
        ulonglong2 v; v.x = acc[jj][0]; v.y = acc[jj][1];
        red2[jj * 512 + tid] = v;
    }
    { ulonglong2 v; v.x = pec0; v.y = pec1; red2p[tid] = v; }
    __syncthreads();

    {
        const int jj = tid >> 5;
        const int dv = tid & 31;
        ull s0 = 0ull, s1 = 0ull;
#pragma unroll
        for (int e = 0; e < 16; ++e) {
            ulonglong2 a = red2[jj * 512 + e * 32 + dv];
            ulonglong2 p = red2p[e * 32 + dv];
            s0 = fadd2(s0, fadd2(a.x, p.x));
            s1 = fadd2(s1, fadd2(a.y, p.y));
        }
        int nb = nb0 + jj;
        if (nb < NBL) {
            float d0, d1, d2, d3;
            unpack2(s0, d0, d1);
            unpack2(s1, d2, d3);
            __half h0 = __float2half_rn(d0), h1 = __float2half_rn(d1);
            __half h2 = __float2half_rn(d2), h3 = __float2half_rn(d3);
            if (t == 0) {   // K: [bh][nb][d]
                u32* dh = (u32*)(g_k16 + ((bh * 256 + nb) * 128 + dv * 4));
                dh[0] = pkhf(h0, h1); dh[1] = pkhf(h2, h3);
            } else {        // V transposed: [bh][d][nb]
                g_vt16[(size_t)(bh * 128 + dv * 4 + 0) * 256 + nb] = h0;
                g_vt16[(size_t)(bh * 128 + dv * 4 + 1) * 256 + nb] = h1;
                g_vt16[(size_t)(bh * 128 + dv * 4 + 2) * 256 + nb] = h2;
                g_vt16[(size_t)(bh * 128 + dv * 4 + 3) * 256 + nb] = h3;
            }
        }
    }
}

// ---------------------------------------------------------------------------
// Attention kernel — fp16 single-pass warp MMA, 2 CTAs/SM.
// grid (64 stile, 16 g, 4 bh), block 256 (8 warps = 2 r-groups x 4 c-groups).
// CTA tile: 64 s-rows x 256 nb. Warp: 32 rows x 64 cols (same frag code
// verified in R8). K staged via cp.async overlapped with Q conversion.
// Softmax in registers; P -> smem (overlays dead K); phase C V chunks
// double-buffered cp.async (buf0 overlays dead Q).
// XOR swizzle: 16B chunk c at row r stored at chunk (c ^ (r&7)).
// SMEM bytes: rmax@0(1K) rsum@1024(1K) | Q@2048(16K) K@18432(64K)
//             P=K(32K used), V0=Q(16K), V1@83968(16K)   total 100,352
// ---------------------------------------------------------------------------
#define SM_RMAX  0
#define SM_RSUM  1024
#define SM_Q     2048
#define SM_K     18432
#define SM_P     SM_K
#define SM_V0    SM_Q
#define SM_V1    83968
#define ATT_SMEM 100352

__global__ __launch_bounds__(256, 2)
void attn_kernel(const float* __restrict__ q, float* __restrict__ out,
                 float* __restrict__ attn, int write_attn)
{
    extern __shared__ char smc[];
    const u32 sb = smem_u32(smc);
    float* rmax = (float*)(smc + SM_RMAX);   // [4 c4][64 rows]
    float* rsum = (float*)(smc + SM_RSUM);

    const int st = blockIdx.x;               // 0..63 (64-row tiles)
    const int g  = blockIdx.y;
    const int bh = blockIdx.z;
    const int b  = bh >> 1, h = bh & 1;
    const int hq = h * GRP + g;
    const int s0 = st * 64;
    const int tid  = threadIdx.x;
    const int w    = tid >> 5;
    const int lane = tid & 31;
    const int r2 = w >> 2, c4 = w & 3;
    const int gq = lane >> 2, tq = lane & 3;
    const int li = lane & 15, lh = lane >> 4;

    const int NVC = st * 4 + 3;              // max valid col count (odd)
    const int KR  = (NVC + 15) & ~15;        // staged K rows (<=256)
    const int rbase = r2 * 32;
    const int cbase = c4 * 64;
    const size_t bhoff = (size_t)bh * 32768;

    // ---- K staging via cp.async (group), overlapped with Q conversion ----
    for (int u = tid; u < KR * 16; u += 256) {
        int nb = u >> 4, c = u & 15;
        u32 dst = sb + SM_K + (u32)nb * 256 + (u32)((c ^ (nb & 7)) << 4);
        CP_A16(dst, g_k16 + bhoff + nb * 128 + c * 8);
    }
    CP_COMMIT();
    for (int u = tid; u < 4096; u += 256) {
        int r = u >> 6, k2 = u & 63;
        float2 qv = *(const float2*)(q + ((size_t)((b * SEQ + s0 + r) * HQN + hq)) * DIM + k2 * 2);
        u32 off = (u32)r * 256 + (((((u32)k2) >> 2) ^ (r & 7)) << 4) + (k2 & 3) * 4;
        *(u32*)(smc + SM_Q + off) = pkhf(__float2half_rn(qv.x), __float2half_rn(qv.y));
    }
    CP_WAIT(0);
    __syncthreads();

    // ---- Phase A: single fp16 pass ----
    float D[16][4];
#pragma unroll
    for (int i = 0; i < 16; ++i) { D[i][0] = D[i][1] = D[i][2] = D[i][3] = 0.f; }

    int jlim = (NVC - cbase + 7) >> 3;
    jlim = (jlim < 0) ? 0 : ((jlim > 8) ? 8 : jlim);
    const int plim = (jlim + 1) >> 1;

    for (int ks = 0; ks < 8; ++ks) {
        u32 a2[2][4];
        const u32 ci = (u32)(ks * 2 + lh);
#pragma unroll
        for (int sp = 0; sp < 2; ++sp) {
            int ri = rbase + sp * 16 + li;
            ldsm4(a2[sp], sb + SM_Q + (u32)ri * 256 + ((ci ^ (ri & 7)) << 4));
        }
        for (int jp = 0; jp < plim; ++jp) {
            int ri = cbase + jp * 16 + li;
            u32 b4[4];
            ldsm4(b4, sb + SM_K + (u32)ri * 256 + ((ci ^ (ri & 7)) << 4));
#pragma unroll
            for (int sp = 0; sp < 2; ++sp) {
                mma16816(D[sp * 8 + 2 * jp],     a2[sp], b4[0], b4[2]);
                mma16816(D[sp * 8 + 2 * jp + 1], a2[sp], b4[1], b4[3]);
            }
        }
    }

    // ---- Softmax: local max -> B1 ----
#pragma unroll
    for (int slot = 0; slot < 4; ++slot) {
        int sp = slot >> 1, hf = slot & 1;
        int row = rbase + sp * 16 + gq + hf * 8;
        int s = s0 + row;
        int nv = (s >= 31) ? (((s - 31) >> 4) + 1) : 0;
        float mloc = -1e30f;
#pragma unroll
        for (int j = 0; j < 8; ++j) {
            int c0 = cbase + j * 8 + 2 * tq;
            if (c0     < nv) mloc = fmaxf(mloc, D[sp * 8 + j][hf * 2]     * SCALE);
            if (c0 + 1 < nv) mloc = fmaxf(mloc, D[sp * 8 + j][hf * 2 + 1] * SCALE);
        }
        mloc = fmaxf(mloc, __shfl_xor_sync(0xffffffffu, mloc, 1));
        mloc = fmaxf(mloc, __shfl_xor_sync(0xffffffffu, mloc, 2));
        if (tq == 0) rmax[c4 * 64 + row] = mloc;
    }
    __syncthreads();                          // B1: Q and K now dead

    // ---- Prefetch V chunks 0/1 (buf0 overlays dead Q) ----
    const int KSC = KR >> 4;                  // valid k16 steps (<=16)
    const int nch = (KSC + 3) >> 2;           // 64-nb chunks (<=4)
    {
        for (int u = tid; u < 1024; u += 256) {
            int dd = u >> 3, n8 = u & 7;
            u32 dst = sb + SM_V0 + (u32)dd * 128 + (u32)((n8 ^ (dd & 7)) << 4);
            CP_A16(dst, g_vt16 + bhoff + dd * 256 + n8 * 8);
        }
        CP_COMMIT();
        if (nch > 1) {
            for (int u = tid; u < 1024; u += 256) {
                int dd = u >> 3, n8 = u & 7;
                u32 dst = sb + SM_V1 + (u32)dd * 128 + (u32)((n8 ^ (dd & 7)) << 4);
                CP_A16(dst, g_vt16 + bhoff + dd * 256 + 64 + n8 * 8);
            }
            CP_COMMIT();
        }
    }

    // ---- Softmax: exp + sum -> B2 ----
#pragma unroll
    for (int slot = 0; slot < 4; ++slot) {
        int sp = slot >> 1, hf = slot & 1;
        int row = rbase + sp * 16 + gq + hf * 8;
        int s = s0 + row;
        int nv = (s >= 31) ? (((s - 31) >> 4) + 1) : 0;
        float m = fmaxf(fmaxf(rmax[row], rmax[64 + row]),
                        fmaxf(rmax[128 + row], rmax[192 + row]));
        float sl = 0.f;
#pragma unroll
        for (int j = 0; j < 8; ++j) {
            int c0 = cbase + j * 8 + 2 * tq;
            float e0 = (c0     < nv) ? __expf(D[sp * 8 + j][hf * 2]     * SCALE - m) : 0.f;
            float e1 = (c0 + 1 < nv) ? __expf(D[sp * 8 + j][hf * 2 + 1] * SCALE - m) : 0.f;
            D[sp * 8 + j][hf * 2]     = e0;
            D[sp * 8 + j][hf * 2 + 1] = e1;
            sl += e0 + e1;
        }
        sl += __shfl_xor_sync(0xffffffffu, sl, 1);
        sl += __shfl_xor_sync(0xffffffffu, sl, 2);
        if (tq == 0) rsum[c4 * 64 + row] = sl;
    }
    __syncthreads();                          // B2

    // ---- Normalize + attn write (scalar: NBL odd!) + P -> smem fp16 ----
#pragma unroll
    for (int slot = 0; slot < 4; ++slot) {
        int sp = slot >> 1, hf = slot & 1;
        int row = rbase + sp * 16 + gq + hf * 8;
        float tot = rsum[row] + rsum[64 + row] + rsum[128 + row] + rsum[192 + row];
        float inv = 1.f / fmaxf(tot, 1e-20f);
        size_t arow = (((size_t)b * HQN + hq) * SEQ + s0 + row) * NBL;
#pragma unroll
        for (int j = 0; j < 8; ++j) {
            int c0 = cbase + j * 8 + 2 * tq;
            float p0 = D[sp * 8 + j][hf * 2]     * inv;
            float p1 = D[sp * 8 + j][hf * 2 + 1] * inv;
            if (write_attn) {
                attn[arow + c0] = p0;                 // c0 <= 254 always
                if (c0 + 1 < NBL) attn[arow + c0 + 1] = p1;
            }
            u32 ch = (u32)(((cbase >> 3) + j) ^ (row & 7));
            u32 off = (u32)row * 512 + (ch << 4) + tq * 4;
            *(u32*)(smc + SM_P + off) = pkhf(__float2half_rn(p0), __float2half_rn(p1));
        }
    }
    __syncthreads();                          // B3: P visible

    // ---- Phase C: double-buffered V chunks, fp16 single pass ----
    const int dbase = c4 * 32;
    float C[8][4];
#pragma unroll
    for (int i = 0; i < 8; ++i) { C[i][0] = C[i][1] = C[i][2] = C[i][3] = 0.f; }

    for (int kc = 0; kc < nch; ++kc) {
        if (kc + 1 < nch) { CP_WAIT(1); } else { CP_WAIT(0); }
        __syncthreads();                      // chunk kc visible to all
        const u32 sbV = sb + ((kc & 1) ? SM_V1 : SM_V0);
        const int kslo = kc * 4;
        const int kshi = min(kslo + 4, KSC);
        for (int ks = kslo; ks < kshi; ++ks) {
            u32 p2[2][4];
            const u32 ciP = (u32)(ks * 2 + lh);
#pragma unroll
            for (int sp = 0; sp < 2; ++sp) {
                int ri = rbase + sp * 16 + li;
                ldsm4(p2[sp], sb + SM_P + (u32)ri * 512 + ((ciP ^ (ri & 7)) << 4));
            }
            const u32 ciV = (u32)((ks - kslo) * 2 + lh);
#pragma unroll
            for (int dp = 0; dp < 2; ++dp) {
                int ri = dbase + dp * 16 + li;
                u32 b4[4];
                ldsm4(b4, sbV + (u32)ri * 128 + ((ciV ^ (ri & 7)) << 4));
#pragma unroll
                for (int sp = 0; sp < 2; ++sp) {
                    mma16816(C[sp * 4 + 2 * dp],     p2[sp], b4[0], b4[2]);
                    mma16816(C[sp * 4 + 2 * dp + 1], p2[sp], b4[1], b4[3]);
                }
            }
        }
        __syncthreads();                      // all reads of chunk kc done
        if (kc + 2 < nch) {
            const u32 dstb = sb + ((kc & 1) ? SM_V1 : SM_V0);
            for (int u = tid; u < 1024; u += 256) {
                int dd = u >> 3, n8 = u & 7;
                u32 dst = dstb + (u32)dd * 128 + (u32)((n8 ^ (dd & 7)) << 4);
                CP_A16(dst, g_vt16 + bhoff + dd * 256 + (kc + 2) * 64 + n8 * 8);
            }
            CP_COMMIT();
        }
    }

    // ---- Store out: (BS, S, HQ, D), float2 per fragment pair ----
#pragma unroll
    for (int slot = 0; slot < 4; ++slot) {
        int sp = slot >> 1, hf = slot & 1;
        int row = rbase + sp * 16 + gq + hf * 8;
        float* op = out + ((size_t)(b * SEQ + s0 + row) * HQN + hq) * DIM + dbase;
#pragma unroll
        for (int dt = 0; dt < 4; ++dt) {
            *(float2*)(op + dt * 8 + 2 * tq) =
                make_float2(C[sp * 4 + dt][hf * 2], C[sp * 4 + dt][hf * 2 + 1]);
        }
    }
}

// ---------------------------------------------------------------------------
extern "C" void kernel_launch(void* const* d_in, const int* in_sizes, int n_in,
                              void* d_out, int out_size)
{
    const float* q   = (const float*)d_in[0];
    const float* k   = (const float*)d_in[1];
    const float* v   = (const float*)d_in[2];
    // d_in[3] = cu_seqlens_k (fixed [0,S,2S]) — unused
    const float* wk  = (const float*)d_in[4];
    const float* wv  = (const float*)d_in[5];
    const float* pek = (const float*)d_in[6];
    const float* pev = (const float*)d_in[7];

    float* out  = (float*)d_out;
    float* attn = out + OUT_ELEMS;
    int write_attn = ((size_t)out_size >= OUT_ELEMS + ATTN_ELEMS) ? 1 : 0;

    const int COMP_SMEM = 272 * 128 * 4;                 // 139,264 B

    cudaFuncSetAttribute(compress_kernel,
                         cudaFuncAttributeMaxDynamicSharedMemorySize, COMP_SMEM);
    cudaFuncSetAttribute(attn_kernel,
                         cudaFuncAttributeMaxDynamicSharedMemorySize, ATT_SMEM);

    compress_kernel<<<dim3(16, 4, 2), 512, COMP_SMEM>>>(k, v, wk, wv, pek, pev);
    attn_kernel<<<dim3(64, 16, 4), 256, ATT_SMEM>>>(q, out, attn, write_attn);
}

// round 13
// speedup vs baseline: 4.2342x; 1.0686x over previous
#include <cuda_runtime.h>
#include <cuda_fp16.h>

// Problem constants (fixed by reference setup)
#define BSZ     2
#define SEQ     4096
#define HQN     32
#define HKV     2
#define DIM     128
#define NBL     255
#define GRP     16
#define SCALE   0.08838834764831845f   // 1/sqrt(128)

#define OUT_ELEMS  ((size_t)BSZ*SEQ*HQN*DIM)            // 33,554,432
#define ATTN_ELEMS ((size_t)BSZ*HQN*SEQ*NBL)            // 66,846,720

typedef unsigned long long ull;
typedef unsigned int       u32;

// Compressed K/V in fp16. nb padded to 256; index 255 stays zero
// (device globals are zero-initialized; row 255 is never written).
// K: [bh][nb(256)][d(128)]   V (pre-transposed): [bh][d(128)][nb(256)]
__device__ __half g_k16 [4*256*128];
__device__ __half g_vt16[4*128*256];

// ---- packed f32x2 helpers (compress kernel) -------------------------------
__device__ __forceinline__ ull pack2(float lo, float hi) {
    ull r; asm("mov.b64 %0,{%1,%2};" : "=l"(r) : "f"(lo), "f"(hi)); return r;
}
__device__ __forceinline__ void unpack2(ull v, float& lo, float& hi) {
    asm("mov.b64 {%0,%1},%2;" : "=f"(lo), "=f"(hi) : "l"(v));
}
__device__ __forceinline__ ull ffma2(ull a, ull b, ull c) {
    ull d; asm("fma.rn.f32x2 %0,%1,%2,%3;" : "=l"(d) : "l"(a), "l"(b), "l"(c)); return d;
}
__device__ __forceinline__ ull fadd2(ull a, ull b) {
    ull d; asm("add.rn.f32x2 %0,%1,%2;" : "=l"(d) : "l"(a), "l"(b)); return d;
}

// ---- warp-MMA helpers (sm_80-class, valid on non-'a' target) --------------
__device__ __forceinline__ u32 smem_u32(const void* p) {
    u32 a; asm("{ .reg .u64 t; cvta.to.shared.u64 t, %1; cvt.u32.u64 %0, t; }"
               : "=r"(a) : "l"(p));
    return a;
}
__device__ __forceinline__ void ldsm4(u32* r, u32 addr) {
    asm volatile("ldmatrix.sync.aligned.m8n8.x4.shared.b16 {%0,%1,%2,%3}, [%4];"
        : "=r"(r[0]), "=r"(r[1]), "=r"(r[2]), "=r"(r[3]) : "r"(addr));
}
__device__ __forceinline__ void mma16816(float* d, const u32* a, u32 b0, u32 b1) {
    asm volatile("mma.sync.aligned.m16n8k16.row.col.f32.f16.f16.f32 "
        "{%0,%1,%2,%3},{%4,%5,%6,%7},{%8,%9},{%0,%1,%2,%3};"
        : "+f"(d[0]), "+f"(d[1]), "+f"(d[2]), "+f"(d[3])
        : "r"(a[0]), "r"(a[1]), "r"(a[2]), "r"(a[3]), "r"(b0), "r"(b1));
}
__device__ __forceinline__ u32 pkhf(__half a, __half b) {
    __half2 t(a, b);                        // .x at low halfword
    return *(u32*)&t;
}
#define CP_A16(dst, src) \
    asm volatile("cp.async.cg.shared.global [%0], [%1], 16;" \
                 :: "r"(dst), "l"(src) : "memory")
#define CP_COMMIT()  asm volatile("cp.async.commit_group;" ::: "memory")
#define CP_WAIT(N)   asm volatile("cp.async.wait_group %0;" :: "n"(N) : "memory")

// ---------------------------------------------------------------------------
// Compression kernel. grid (16, 4, 2), block 512 (unchanged from R9).
// ---------------------------------------------------------------------------
__global__ __launch_bounds__(512, 1)
void compress_kernel(const float* __restrict__ kin, const float* __restrict__ vin,
                     const float* __restrict__ wk,  const float* __restrict__ wv,
                     const float* __restrict__ pek, const float* __restrict__ pev)
{
    extern __shared__ float xs[];            // 272*128 floats = 139,264 B

    const int nbg = blockIdx.x;
    const int bh  = blockIdx.y;              // b*2+h
    const int b   = bh >> 1, h = bh & 1;
    const int t   = blockIdx.z;              // 0=k, 1=v

    const float* x  = t ? vin : kin;
    const float* w  = t ? wv  : wk;
    const float* pe = t ? pev : pek;

    const int tid  = threadIdx.x;
    const int dvec = tid & 31;
    const int ep   = tid >> 5;               // 0..15, 2 blks each

    const int nb0  = nbg * 16;
    const int JN   = (nbg == 15) ? 15 : 16;
    const int R    = JN * 16 + 16;
    const int row0 = nbg * 256;

    for (int i = tid; i < R * 128; i += 512) {
        int r = i >> 7, dd = i & 127;
        xs[i] = x[((b * SEQ + row0 + r) * HKV + h) * DIM + dd];
    }
    __syncthreads();

    ull acc[16][2];
#pragma unroll
    for (int j = 0; j < 16; ++j) { acc[j][0] = 0ull; acc[j][1] = 0ull; }
    ull pec0 = 0ull, pec1 = 0ull;

#pragma unroll
    for (int bq = 0; bq < 2; ++bq) {
        const int blk = ep * 2 + bq;
        const float* xb  = xs + blk * 128;
        const float* peb = pe + blk * 128;
        const ull*   wb  = (const ull*)w + (size_t)blk * 8192 + dvec * 2;
#pragma unroll 2
        for (int dd = 0; dd < 128; ++dd) {
            ulonglong2 w2 = *(const ulonglong2*)(wb + (size_t)dd * 64);
            float pv = peb[dd];
            ull pv2 = pack2(pv, pv);
            pec0 = ffma2(pv2, w2.x, pec0);
            pec1 = ffma2(pv2, w2.y, pec1);
#pragma unroll
            for (int jj = 0; jj < 16; ++jj) {
                float xv = xb[jj * 2048 + dd];
                ull x2 = pack2(xv, xv);
                acc[jj][0] = ffma2(x2, w2.x, acc[jj][0]);
                acc[jj][1] = ffma2(x2, w2.y, acc[jj][1]);
            }
        }
    }

    __syncthreads();
    ulonglong2* red2  = (ulonglong2*)xs;
    ulonglong2* red2p = red2 + 16 * 512;

#pragma unroll
    for (int jj = 0; jj < 16; ++jj) {
        ulonglong2 v; v.x = acc[jj][0]; v.y = acc[jj][1];
        red2[jj * 512 + tid] = v;
    }
    { ulonglong2 v; v.x = pec0; v.y = pec1; red2p[tid] = v; }
    __syncthreads();

    {
        const int jj = tid >> 5;
        const int dv = tid & 31;
        ull s0 = 0ull, s1 = 0ull;
#pragma unroll
        for (int e = 0; e < 16; ++e) {
            ulonglong2 a = red2[jj * 512 + e * 32 + dv];
            ulonglong2 p = red2p[e * 32 + dv];
            s0 = fadd2(s0, fadd2(a.x, p.x));
            s1 = fadd2(s1, fadd2(a.y, p.y));
        }
        int nb = nb0 + jj;
        if (nb < NBL) {
            float d0, d1, d2, d3;
            unpack2(s0, d0, d1);
            unpack2(s1, d2, d3);
            __half h0 = __float2half_rn(d0), h1 = __float2half_rn(d1);
            __half h2 = __float2half_rn(d2), h3 = __float2half_rn(d3);
            if (t == 0) {   // K: [bh][nb][d]
                u32* dh = (u32*)(g_k16 + ((bh * 256 + nb) * 128 + dv * 4));
                dh[0] = pkhf(h0, h1); dh[1] = pkhf(h2, h3);
            } else {        // V transposed: [bh][d][nb]
                g_vt16[(size_t)(bh * 128 + dv * 4 + 0) * 256 + nb] = h0;
                g_vt16[(size_t)(bh * 128 + dv * 4 + 1) * 256 + nb] = h1;
                g_vt16[(size_t)(bh * 128 + dv * 4 + 2) * 256 + nb] = h2;
                g_vt16[(size_t)(bh * 128 + dv * 4 + 3) * 256 + nb] = h3;
            }
        }
    }
}

// ---------------------------------------------------------------------------
// Attention kernel — fp16 warp MMA, 3 CTAs/SM.
// grid (64, 16, 4), block 256, __launch_bounds__(256,3) (regs<=83).
// st = 63 - blockIdx.x (heavy tiles first).
// K streamed in two 128-row halves through one 32KB buffer; phase A warp
// covers 32 cols per half (D[2][8][4]). V: 32-nb chunks, stride 80B
// (5x16B units, coprime 8 -> conflict-free ldmatrix, no XOR), two dedicated
// buffers, prefetched from kernel start.
// cp.async GROUP LEDGER (both R10/R11 bugs fixed):
//   (1) exactly THREE groups always committed up front — K-half0, V0, V1
//       (V1 group EMPTY when nch==1; empty groups complete immediately) so
//       CP_WAIT(2) always drains K-half0;
//   (2) phase C waits are CONDITIONAL: kc<nch-1 -> CP_WAIT(1) (pending ⊆
//       {V_kc, V_kc+1}, drains V_kc); kc==nch-1 -> CP_WAIT(0) (the last
//       chunk has NO younger group behind it — CP_WAIT(1) would let it
//       remain in flight; this was the R10/R11 corruption).
// SMEM: rmax@0 1K | rsum@1024 1K | Q@2048 16K | K/P@18432 32K |
//       V0@51200 10.25K | V1@61440 10.25K     total 71,680 B
// ---------------------------------------------------------------------------
#define SM_RMAX  0
#define SM_RSUM  1024
#define SM_Q     2048
#define SM_K     18432
#define SM_P     SM_K
#define SM_V0    51200
#define SM_V1    61440
#define ATT_SMEM 71680

__global__ __launch_bounds__(256, 3)
void attn_kernel(const float* __restrict__ q, float* __restrict__ out,
                 float* __restrict__ attn, int write_attn)
{
    extern __shared__ char smc[];
    const u32 sb = smem_u32(smc);
    float* rmax = (float*)(smc + SM_RMAX);   // [4 c4][64 rows]
    float* rsum = (float*)(smc + SM_RSUM);

    const int st = 63 - blockIdx.x;          // heavy-first
    const int g  = blockIdx.y;
    const int bh = blockIdx.z;
    const int b  = bh >> 1, h = bh & 1;
    const int hq = h * GRP + g;
    const int s0 = st * 64;
    const int tid  = threadIdx.x;
    const int w    = tid >> 5;
    const int lane = tid & 31;
    const int r2 = w >> 2, c4 = w & 3;
    const int gq = lane >> 2, tq = lane & 3;
    const int li = lane & 15, lh = lane >> 4;

    const int NVC = st * 4 + 3;              // max valid col count (odd)
    const int KR  = (NVC + 15) & ~15;        // total valid K rows (<=256)
    const int KR0 = min(KR, 128);
    const int KR1 = KR - KR0;                // >0 iff st>=32
    const int rbase = r2 * 32;
    const size_t bhoff = (size_t)bh * 32768;

    const int KSC = KR >> 4;                 // k16 steps for phase C (<=16)
    const int nch = (KSC + 1) >> 1;          // 32-nb V chunks (<=8)

    // ---- group 1: K half0 ----
    for (int u = tid; u < KR0 * 16; u += 256) {
        int nb = u >> 4, c = u & 15;
        u32 dst = sb + SM_K + (u32)nb * 256 + (u32)((c ^ (nb & 7)) << 4);
        CP_A16(dst, g_k16 + bhoff + nb * 128 + c * 8);
    }
    CP_COMMIT();
    // ---- group 2: V chunk 0 ----
    for (int u = tid; u < 512; u += 256) {
        int dd = u >> 2, cc = u & 3;
        CP_A16(sb + SM_V0 + (u32)dd * 80 + (u32)cc * 16,
               g_vt16 + bhoff + dd * 256 + cc * 8);
    }
    CP_COMMIT();
    // ---- group 3: V chunk 1 (EMPTY group when nch==1 — keeps the count) ----
    if (nch > 1) {
        for (int u = tid; u < 512; u += 256) {
            int dd = u >> 2, cc = u & 3;
            CP_A16(sb + SM_V1 + (u32)dd * 80 + (u32)cc * 16,
                   g_vt16 + bhoff + dd * 256 + 32 + cc * 8);
        }
    }
    CP_COMMIT();                              // ALWAYS the 3rd group
    // ---- Stage Q (f32 -> fp16), swizzled 256B rows ----
    for (int u = tid; u < 4096; u += 256) {
        int r = u >> 6, k2 = u & 63;
        float2 qv = *(const float2*)(q + ((size_t)((b * SEQ + s0 + r) * HQN + hq)) * DIM + k2 * 2);
        u32 off = (u32)r * 256 + (((((u32)k2) >> 2) ^ (r & 7)) << 4) + (k2 & 3) * 4;
        *(u32*)(smc + SM_Q + off) = pkhf(__float2half_rn(qv.x), __float2half_rn(qv.y));
    }
    CP_WAIT(2);                               // drains K half0 (3 groups committed)
    __syncthreads();

    // ---- Phase A: D[2 half][8 tile][4]; warp covers 32 cols per half ----
    float D[16][4];
#pragma unroll
    for (int i = 0; i < 16; ++i) { D[i][0] = D[i][1] = D[i][2] = D[i][3] = 0.f; }

#pragma unroll
    for (int hk = 0; hk < 2; ++hk) {
        if (hk == 1) {
            if (KR1 <= 0) break;
            __syncthreads();                  // all reads of K half0 done
            for (int u = tid; u < KR1 * 16; u += 256) {
                int nb = u >> 4, c = u & 15;
                u32 dst = sb + SM_K + (u32)nb * 256 + (u32)((c ^ (nb & 7)) << 4);
                CP_A16(dst, g_k16 + bhoff + (128 + nb) * 128 + c * 8);
            }
            CP_COMMIT();
            CP_WAIT(0);                       // drains V0/V1 too (issued early)
            __syncthreads();
        }
        const int cw = hk * 128 + c4 * 32;    // warp's first score col
        int jt = (NVC - cw + 7) >> 3;
        jt = (jt < 0) ? 0 : ((jt > 4) ? 4 : jt);
        const int ph = (jt + 1) >> 1;         // 16-col pairs (<=2)
        for (int ks = 0; ks < 8; ++ks) {
            u32 a2[2][4];
            const u32 ci = (u32)(ks * 2 + lh);
#pragma unroll
            for (int sp = 0; sp < 2; ++sp) {
                int ri = rbase + sp * 16 + li;
                ldsm4(a2[sp], sb + SM_Q + (u32)ri * 256 + ((ci ^ (ri & 7)) << 4));
            }
            for (int jp = 0; jp < ph; ++jp) {
                int ri = c4 * 32 + jp * 16 + li;      // local K row
                u32 b4[4];
                ldsm4(b4, sb + SM_K + (u32)ri * 256 + ((ci ^ (ri & 7)) << 4));
#pragma unroll
                for (int sp = 0; sp < 2; ++sp) {
                    mma16816(D[hk * 8 + sp * 4 + 2 * jp],     a2[sp], b4[0], b4[2]);
                    mma16816(D[hk * 8 + sp * 4 + 2 * jp + 1], a2[sp], b4[1], b4[3]);
                }
            }
        }
    }

    // ---- Softmax: local max -> B1 ----
#pragma unroll
    for (int slot = 0; slot < 4; ++slot) {
        int sp = slot >> 1, hf = slot & 1;
        int row = rbase + sp * 16 + gq + hf * 8;
        int s = s0 + row;
        int nv = (s >= 31) ? (((s - 31) >> 4) + 1) : 0;
        float mloc = -1e30f;
#pragma unroll
        for (int hk = 0; hk < 2; ++hk)
#pragma unroll
            for (int j = 0; j < 4; ++j) {
                int c0 = hk * 128 + c4 * 32 + j * 8 + 2 * tq;
                float* dd = D[hk * 8 + sp * 4 + j];
                if (c0     < nv) mloc = fmaxf(mloc, dd[hf * 2]     * SCALE);
                if (c0 + 1 < nv) mloc = fmaxf(mloc, dd[hf * 2 + 1] * SCALE);
            }
        mloc = fmaxf(mloc, __shfl_xor_sync(0xffffffffu, mloc, 1));
        mloc = fmaxf(mloc, __shfl_xor_sync(0xffffffffu, mloc, 2));
        if (tq == 0) rmax[c4 * 64 + row] = mloc;
    }
    __syncthreads();                          // B1

    // ---- Softmax: exp + sum -> B2 ----
#pragma unroll
    for (int slot = 0; slot < 4; ++slot) {
        int sp = slot >> 1, hf = slot & 1;
        int row = rbase + sp * 16 + gq + hf * 8;
        int s = s0 + row;
        int nv = (s >= 31) ? (((s - 31) >> 4) + 1) : 0;
        float m = fmaxf(fmaxf(rmax[row], rmax[64 + row]),
                        fmaxf(rmax[128 + row], rmax[192 + row]));
        float sl = 0.f;
#pragma unroll
        for (int hk = 0; hk < 2; ++hk)
#pragma unroll
            for (int j = 0; j < 4; ++j) {
                int c0 = hk * 128 + c4 * 32 + j * 8 + 2 * tq;
                float* dd = D[hk * 8 + sp * 4 + j];
                float e0 = (c0     < nv) ? __expf(dd[hf * 2]     * SCALE - m) : 0.f;
                float e1 = (c0 + 1 < nv) ? __expf(dd[hf * 2 + 1] * SCALE - m) : 0.f;
                dd[hf * 2]     = e0;
                dd[hf * 2 + 1] = e1;
                sl += e0 + e1;
            }
        sl += __shfl_xor_sync(0xffffffffu, sl, 1);
        sl += __shfl_xor_sync(0xffffffffu, sl, 2);
        if (tq == 0) rsum[c4 * 64 + row] = sl;
    }
    __syncthreads();                          // B2: K reads done -> P may overlay

    // ---- Normalize + attn write (scalar: NBL odd!) + P -> smem fp16 ----
#pragma unroll
    for (int slot = 0; slot < 4; ++slot) {
        int sp = slot >> 1, hf = slot & 1;
        int row = rbase + sp * 16 + gq + hf * 8;
        float tot = rsum[row] + rsum[64 + row] + rsum[128 + row] + rsum[192 + row];
        float inv = 1.f / fmaxf(tot, 1e-20f);
        size_t arow = (((size_t)b * HQN + hq) * SEQ + s0 + row) * NBL;
#pragma unroll
        for (int hk = 0; hk < 2; ++hk)
#pragma unroll
            for (int j = 0; j < 4; ++j) {
                int c0 = hk * 128 + c4 * 32 + j * 8 + 2 * tq;
                float* dd = D[hk * 8 + sp * 4 + j];
                float p0 = dd[hf * 2]     * inv;
                float p1 = dd[hf * 2 + 1] * inv;
                if (write_attn) {
                    attn[arow + c0] = p0;             // c0 <= 254 always
                    if (c0 + 1 < NBL) attn[arow + c0 + 1] = p1;
                }
                u32 ch = (u32)((hk * 16 + c4 * 4 + j) ^ (row & 7));
                u32 off = (u32)row * 512 + (ch << 4) + tq * 4;
                *(u32*)(smc + SM_P + off) = pkhf(__float2half_rn(p0), __float2half_rn(p1));
            }
    }
    __syncthreads();                          // B3: P visible

    // ---- Phase C: 32-nb V chunks, double-buffered ----
    const int dbase = c4 * 32;
    float C[8][4];
#pragma unroll
    for (int i = 0; i < 8; ++i) { C[i][0] = C[i][1] = C[i][2] = C[i][3] = 0.f; }

    for (int kc = 0; kc < nch; ++kc) {
        if (kc + 1 < nch) { CP_WAIT(1); }     // pending ⊆ {V_kc, V_kc+1} -> drains V_kc
        else             { CP_WAIT(0); }      // LAST chunk: nothing younger -> full drain
        __syncthreads();
        const u32 sbV = sb + ((kc & 1) ? SM_V1 : SM_V0);
        const int kslo = kc * 2;
        const int kshi = min(kslo + 2, KSC);
        for (int ks = kslo; ks < kshi; ++ks) {
            u32 p2[2][4];
            const u32 ciP = (u32)(ks * 2 + lh);
#pragma unroll
            for (int sp = 0; sp < 2; ++sp) {
                int ri = rbase + sp * 16 + li;
                ldsm4(p2[sp], sb + SM_P + (u32)ri * 512 + ((ciP ^ (ri & 7)) << 4));
            }
            const u32 ciV = (u32)((ks - kslo) * 2 + lh);
#pragma unroll
            for (int dp = 0; dp < 2; ++dp) {
                int ri = dbase + dp * 16 + li;
                u32 b4[4];
                ldsm4(b4, sbV + (u32)ri * 80 + ciV * 16);
#pragma unroll
                for (int sp = 0; sp < 2; ++sp) {
                    mma16816(C[sp * 4 + 2 * dp],     p2[sp], b4[0], b4[2]);
                    mma16816(C[sp * 4 + 2 * dp + 1], p2[sp], b4[1], b4[3]);
                }
            }
        }
        __syncthreads();                      // reads of chunk kc done
        if (kc + 2 < nch) {
            const u32 dstb = sb + ((kc & 1) ? SM_V1 : SM_V0);
            for (int u = tid; u < 512; u += 256) {
                int dd = u >> 2, cc = u & 3;
                CP_A16(dstb + (u32)dd * 80 + (u32)cc * 16,
                       g_vt16 + bhoff + dd * 256 + (kc + 2) * 32 + cc * 8);
            }
            CP_COMMIT();
        }
    }

    // ---- Store out: (BS, S, HQ, D), float2 per fragment pair ----
#pragma unroll
    for (int slot = 0; slot < 4; ++slot) {
        int sp = slot >> 1, hf = slot & 1;
        int row = rbase + sp * 16 + gq + hf * 8;
        float* op = out + ((size_t)(b * SEQ + s0 + row) * HQN + hq) * DIM + dbase;
#pragma unroll
        for (int dt = 0; dt < 4; ++dt) {
            *(float2*)(op + dt * 8 + 2 * tq) =
                make_float2(C[sp * 4 + dt][hf * 2], C[sp * 4 + dt][hf * 2 + 1]);
        }
    }
}

// ---------------------------------------------------------------------------
extern "C" void kernel_launch(void* const* d_in, const int* in_sizes, int n_in,
                              void* d_out, int out_size)
{
    const float* q   = (const float*)d_in[0];
    const float* k   = (const float*)d_in[1];
    const float* v   = (const float*)d_in[2];
    // d_in[3] = cu_seqlens_k (fixed [0,S,2S]) — unused
    const float* wk  = (const float*)d_in[4];
    const float* wv  = (const float*)d_in[5];
    const float* pek = (const float*)d_in[6];
    const float* pev = (const float*)d_in[7];

    float* out  = (float*)d_out;
    float* attn = out + OUT_ELEMS;
    int write_attn = ((size_t)out_size >= OUT_ELEMS + ATTN_ELEMS) ? 1 : 0;

    const int COMP_SMEM = 272 * 128 * 4;                 // 139,264 B

    cudaFuncSetAttribute(compress_kernel,
                         cudaFuncAttributeMaxDynamicSharedMemorySize, COMP_SMEM);
    cudaFuncSetAttribute(attn_kernel,
                         cudaFuncAttributeMaxDynamicSharedMemorySize, ATT_SMEM);

    compress_kernel<<<dim3(16, 4, 2), 512, COMP_SMEM>>>(k, v, wk, wv, pek, pev);
    attn_kernel<<<dim3(64, 16, 4), 256, ATT_SMEM>>>(q, out, attn, write_attn);
}

// round 14
// speedup vs baseline: 4.7246x; 1.1158x over previous
#include <cuda_runtime.h>
#include <cuda_fp16.h>

// Problem constants (fixed by reference setup)
#define BSZ     2
#define SEQ     4096
#define HQN     32
#define HKV     2
#define DIM     128
#define NBL     255
#define GRP     16
#define SCALE   0.08838834764831845f   // 1/sqrt(128)

#define OUT_ELEMS  ((size_t)BSZ*SEQ*HQN*DIM)            // 33,554,432
#define ATTN_ELEMS ((size_t)BSZ*HQN*SEQ*NBL)            // 66,846,720

typedef unsigned long long ull;
typedef unsigned int       u32;

// Compressed K/V in fp16. nb padded to 256; index 255 stays zero
// (device globals are zero-initialized; row 255 is never written).
// K: [bh][nb(256)][d(128)]   V (pre-transposed): [bh][d(128)][nb(256)]
__device__ __half g_k16 [4*256*128];
__device__ __half g_vt16[4*128*256];
// W pre-converted to fp16: [t][e(4096)][d(128)]
__device__ __half g_w16 [2*4096*128];

// ---- warp-MMA helpers (sm_80-class, valid on non-'a' target) --------------
__device__ __forceinline__ u32 smem_u32(const void* p) {
    u32 a; asm("{ .reg .u64 t; cvta.to.shared.u64 t, %1; cvt.u32.u64 %0, t; }"
               : "=r"(a) : "l"(p));
    return a;
}
__device__ __forceinline__ void ldsm4(u32* r, u32 addr) {
    asm volatile("ldmatrix.sync.aligned.m8n8.x4.shared.b16 {%0,%1,%2,%3}, [%4];"
        : "=r"(r[0]), "=r"(r[1]), "=r"(r[2]), "=r"(r[3]) : "r"(addr));
}
__device__ __forceinline__ void ldsm4t(u32* r, u32 addr) {
    asm volatile("ldmatrix.sync.aligned.m8n8.x4.trans.shared.b16 {%0,%1,%2,%3}, [%4];"
        : "=r"(r[0]), "=r"(r[1]), "=r"(r[2]), "=r"(r[3]) : "r"(addr));
}
__device__ __forceinline__ void mma16816(float* d, const u32* a, u32 b0, u32 b1) {
    asm volatile("mma.sync.aligned.m16n8k16.row.col.f32.f16.f16.f32 "
        "{%0,%1,%2,%3},{%4,%5,%6,%7},{%8,%9},{%0,%1,%2,%3};"
        : "+f"(d[0]), "+f"(d[1]), "+f"(d[2]), "+f"(d[3])
        : "r"(a[0]), "r"(a[1]), "r"(a[2]), "r"(a[3]), "r"(b0), "r"(b1));
}
__device__ __forceinline__ u32 pkhf(__half a, __half b) {
    __half2 t(a, b);                        // .x at low halfword
    return *(u32*)&t;
}
#define CP_A16(dst, src) \
    asm volatile("cp.async.cg.shared.global [%0], [%1], 16;" \
                 :: "r"(dst), "l"(src) : "memory")
#define CP_COMMIT()  asm volatile("cp.async.commit_group;" ::: "memory")
#define CP_WAIT(N)   asm volatile("cp.async.wait_group %0;" :: "n"(N) : "memory")

// ---------------------------------------------------------------------------
// W fp32 -> fp16 conversion. grid (512, 2), block 256. 131072 float4 per t.
// ---------------------------------------------------------------------------
__global__ __launch_bounds__(256)
void wconv_kernel(const float* __restrict__ wk, const float* __restrict__ wv)
{
    const float* src = blockIdx.y ? wv : wk;
    __half* dst = g_w16 + (size_t)blockIdx.y * 524288;
    int i = blockIdx.x * 256 + threadIdx.x;
    float4 v = ((const float4*)src)[i];
    uint2 o;
    o.x = pkhf(__float2half_rn(v.x), __float2half_rn(v.y));
    o.y = pkhf(__float2half_rn(v.z), __float2half_rn(v.w));
    ((uint2*)dst)[i] = o;
}

// ---------------------------------------------------------------------------
// Compression via HMMA. grid (16 nbg, 4 bh, 2 t), block 256 (8 warps).
// Per CTA: C[16 nb, 128 d] = A[16, 4096]·W[4096, 128], K streamed as 32
// blk-chunks of 128 e-values. A[nb, blk*128+dd] = x[(nb0+nb)*16+blk][dd] +
// pe[blk][dd], staged fp32-add + fp16-convert into a 4KB swizzled buffer.
// W chunks (32KB fp16, k-major [e][d]) stream via cp.async double-buffer
// from g_w16; B fragments via ldmatrix.x4.trans. Warp w owns d-cols w*16.
// cp.async LEDGER: prologue commits w0, w1; every loop iter commits exactly
// ONE group (empty when blk+2 >= 32) after the compute-done sync, then
// CP_WAIT(1) drains w_{blk+1}. Buffer reuse is barrier-protected.
// SMEM: A 2x4KB @0 | W 2x32KB @8192   total 73,728 B   (2 CTAs/SM)
// ---------------------------------------------------------------------------
#define CM_A_OFF 0
#define CM_W_OFF 8192
#define CM_SMEM  73728

__global__ __launch_bounds__(256, 2)
void compress_mma(const float* __restrict__ kin, const float* __restrict__ vin,
                  const float* __restrict__ pek, const float* __restrict__ pev)
{
    extern __shared__ char smc[];
    const u32 sb = smem_u32(smc);

    const int nbg = blockIdx.x;              // 0..15
    const int bh  = blockIdx.y;              // b*2+h
    const int b   = bh >> 1, h = bh & 1;
    const int t   = blockIdx.z;              // 0=k, 1=v

    const float*  x    = t ? vin : kin;
    const float*  pe   = t ? pev : pek;
    const __half* w16g = g_w16 + (size_t)t * 524288;

    const int tid  = threadIdx.x;
    const int w    = tid >> 5;
    const int lane = tid & 31;
    const int li = lane & 15, lh = lane >> 4;
    const int gq = lane >> 2, tq = lane & 3;
    const int dw = w * 16;                   // warp's d-range [dw, dw+16)
    const int nb0 = nbg * 16;

    // -- A stage: chunk blk -> Abuf[buf] (16 rows x 128 e fp16, swizzled) --
    auto a_stage = [&](int blk, int buf) {
        const int row = tid >> 4;            // 0..15
        const int c2  = tid & 15;
        const int nb  = nb0 + row;
        const float* xrowp = x + ((size_t)(b * SEQ + nb * 16 + blk) * HKV + h) * DIM;
        const float* pep   = pe + blk * 128;
        char* abase = smc + CM_A_OFF + buf * 4096;
#pragma unroll
        for (int j = 0; j < 4; ++j) {
            int e2 = c2 + 16 * j;            // u32 index; dd = e2*2
            float2 xv = make_float2(0.f, 0.f);
            if (nb < NBL) xv = *(const float2*)(xrowp + e2 * 2);
            float2 pv = *(const float2*)(pep + e2 * 2);
            u32 off = (u32)row * 256 + ((((u32)e2 >> 2) ^ (row & 7)) << 4) + (e2 & 3) * 4;
            *(u32*)(abase + off) = pkhf(__float2half_rn(xv.x + pv.x),
                                        __float2half_rn(xv.y + pv.y));
        }
    };
    // -- W stage: chunk blk -> Wbuf[buf] via cp.async (128 e x 128 d fp16) --
    auto w_stage = [&](int blk, int buf) {
        const __half* wp = w16g + (size_t)blk * 16384;
        for (int u = tid; u < 2048; u += 256) {
            int e = u >> 4, cc = u & 15;
            u32 dst = sb + CM_W_OFF + buf * 32768
                    + (u32)e * 256 + (u32)((cc ^ (e & 7)) << 4);
            CP_A16(dst, wp + e * 128 + cc * 8);
        }
    };

    float acc[8];
#pragma unroll
    for (int i = 0; i < 8; ++i) acc[i] = 0.f;

    // prologue: w0, w1 committed; A0 staged; drain w0
    w_stage(0, 0); CP_COMMIT();
    w_stage(1, 1); CP_COMMIT();
    a_stage(0, 0);
    CP_WAIT(1);
    __syncthreads();

    for (int blk = 0; blk < 32; ++blk) {
        const int buf = blk & 1;
        // compute chunk blk: 8 k16 steps
#pragma unroll
        for (int ks = 0; ks < 8; ++ks) {
            u32 a4[4];
            ldsm4(a4, sb + CM_A_OFF + buf * 4096
                      + (u32)li * 256 + ((((u32)(ks * 2 + lh)) ^ (li & 7)) << 4));
            u32 b4[4];
            int e = ks * 16 + ((lane >> 3) & 1) * 8 + (lane & 7);
            u32 cd = (u32)((dw >> 3) + (lane >> 4));
            ldsm4t(b4, sb + CM_W_OFF + buf * 32768
                       + (u32)e * 256 + ((cd ^ (e & 7)) << 4));
            mma16816(acc,     a4, b4[0], b4[1]);   // n-tile dw..dw+8
            mma16816(acc + 4, a4, b4[2], b4[3]);   // n-tile dw+8..dw+16
        }
        __syncthreads();                      // all reads of buf done
        if (blk + 2 < 32) w_stage(blk + 2, buf);
        CP_COMMIT();                          // ALWAYS one group per iter
        if (blk + 1 < 32) a_stage(blk + 1, (blk + 1) & 1);
        CP_WAIT(1);                           // drains w_{blk+1}
        __syncthreads();
    }

    // -- Epilogue: C frags -> global fp16 outputs --
    const int nbr0 = nb0 + gq, nbr1 = nb0 + gq + 8;
    if (t == 0) {
        __half* base = g_k16 + (size_t)(bh * 256) * 128;
        if (nbr0 < NBL) {
            __half* p = base + (size_t)nbr0 * 128 + dw + 2 * tq;
            *(u32*)p       = pkhf(__float2half_rn(acc[0]), __float2half_rn(acc[1]));
            *(u32*)(p + 8) = pkhf(__float2half_rn(acc[4]), __float2half_rn(acc[5]));
        }
        if (nbr1 < NBL) {
            __half* p = base + (size_t)nbr1 * 128 + dw + 2 * tq;
            *(u32*)p       = pkhf(__float2half_rn(acc[2]), __float2half_rn(acc[3]));
            *(u32*)(p + 8) = pkhf(__float2half_rn(acc[6]), __float2half_rn(acc[7]));
        }
    } else {
        __half* vb = g_vt16 + (size_t)(bh * 128) * 256;
        const int d0 = dw + 2 * tq;
        if (nbr0 < NBL) {
            vb[(size_t)d0 * 256 + nbr0]       = __float2half_rn(acc[0]);
            vb[(size_t)(d0 + 1) * 256 + nbr0] = __float2half_rn(acc[1]);
            vb[(size_t)(d0 + 8) * 256 + nbr0] = __float2half_rn(acc[4]);
            vb[(size_t)(d0 + 9) * 256 + nbr0] = __float2half_rn(acc[5]);
        }
        if (nbr1 < NBL) {
            vb[(size_t)d0 * 256 + nbr1]       = __float2half_rn(acc[2]);
            vb[(size_t)(d0 + 1) * 256 + nbr1] = __float2half_rn(acc[3]);
            vb[(size_t)(d0 + 8) * 256 + nbr1] = __float2half_rn(acc[6]);
            vb[(size_t)(d0 + 9) * 256 + nbr1] = __float2half_rn(acc[7]);
        }
    }
}

// ---------------------------------------------------------------------------
// Attention kernel — fp16 warp MMA, 3 CTAs/SM. VERBATIM from R12 (passing).
// ---------------------------------------------------------------------------
#define SM_RMAX  0
#define SM_RSUM  1024
#define SM_Q     2048
#define SM_K     18432
#define SM_P     SM_K
#define SM_V0    51200
#define SM_V1    61440
#define ATT_SMEM 71680

__global__ __launch_bounds__(256, 3)
void attn_kernel(const float* __restrict__ q, float* __restrict__ out,
                 float* __restrict__ attn, int write_attn)
{
    extern __shared__ char smc[];
    const u32 sb = smem_u32(smc);
    float* rmax = (float*)(smc + SM_RMAX);   // [4 c4][64 rows]
    float* rsum = (float*)(smc + SM_RSUM);

    const int st = 63 - blockIdx.x;          // heavy-first
    const int g  = blockIdx.y;
    const int bh = blockIdx.z;
    const int b  = bh >> 1, h = bh & 1;
    const int hq = h * GRP + g;
    const int s0 = st * 64;
    const int tid  = threadIdx.x;
    const int w    = tid >> 5;
    const int lane = tid & 31;
    const int r2 = w >> 2, c4 = w & 3;
    const int gq = lane >> 2, tq = lane & 3;
    const int li = lane & 15, lh = lane >> 4;

    const int NVC = st * 4 + 3;              // max valid col count (odd)
    const int KR  = (NVC + 15) & ~15;        // total valid K rows (<=256)
    const int KR0 = min(KR, 128);
    const int KR1 = KR - KR0;                // >0 iff st>=32
    const int rbase = r2 * 32;
    const size_t bhoff = (size_t)bh * 32768;

    const int KSC = KR >> 4;                 // k16 steps for phase C (<=16)
    const int nch = (KSC + 1) >> 1;          // 32-nb V chunks (<=8)

    // ---- group 1: K half0 ----
    for (int u = tid; u < KR0 * 16; u += 256) {
        int nb = u >> 4, c = u & 15;
        u32 dst = sb + SM_K + (u32)nb * 256 + (u32)((c ^ (nb & 7)) << 4);
        CP_A16(dst, g_k16 + bhoff + nb * 128 + c * 8);
    }
    CP_COMMIT();
    // ---- group 2: V chunk 0 ----
    for (int u = tid; u < 512; u += 256) {
        int dd = u >> 2, cc = u & 3;
        CP_A16(sb + SM_V0 + (u32)dd * 80 + (u32)cc * 16,
               g_vt16 + bhoff + dd * 256 + cc * 8);
    }
    CP_COMMIT();
    // ---- group 3: V chunk 1 (EMPTY group when nch==1 — keeps the count) ----
    if (nch > 1) {
        for (int u = tid; u < 512; u += 256) {
            int dd = u >> 2, cc = u & 3;
            CP_A16(sb + SM_V1 + (u32)dd * 80 + (u32)cc * 16,
                   g_vt16 + bhoff + dd * 256 + 32 + cc * 8);
        }
    }
    CP_COMMIT();                              // ALWAYS the 3rd group
    // ---- Stage Q (f32 -> fp16), swizzled 256B rows ----
    for (int u = tid; u < 4096; u += 256) {
        int r = u >> 6, k2 = u & 63;
        float2 qv = *(const float2*)(q + ((size_t)((b * SEQ + s0 + r) * HQN + hq)) * DIM + k2 * 2);
        u32 off = (u32)r * 256 + (((((u32)k2) >> 2) ^ (r & 7)) << 4) + (k2 & 3) * 4;
        *(u32*)(smc + SM_Q + off) = pkhf(__float2half_rn(qv.x), __float2half_rn(qv.y));
    }
    CP_WAIT(2);                               // drains K half0 (3 groups committed)
    __syncthreads();

    // ---- Phase A: D[2 half][8 tile][4]; warp covers 32 cols per half ----
    float D[16][4];
#pragma unroll
    for (int i = 0; i < 16; ++i) { D[i][0] = D[i][1] = D[i][2] = D[i][3] = 0.f; }

#pragma unroll
    for (int hk = 0; hk < 2; ++hk) {
        if (hk == 1) {
            if (KR1 <= 0) break;
            __syncthreads();                  // all reads of K half0 done
            for (int u = tid; u < KR1 * 16; u += 256) {
                int nb = u >> 4, c = u & 15;
                u32 dst = sb + SM_K + (u32)nb * 256 + (u32)((c ^ (nb & 7)) << 4);
                CP_A16(dst, g_k16 + bhoff + (128 + nb) * 128 + c * 8);
            }
            CP_COMMIT();
            CP_WAIT(0);                       // drains V0/V1 too (issued early)
            __syncthreads();
        }
        const int cw = hk * 128 + c4 * 32;    // warp's first score col
        int jt = (NVC - cw + 7) >> 3;
        jt = (jt < 0) ? 0 : ((jt > 4) ? 4 : jt);
        const int ph = (jt + 1) >> 1;         // 16-col pairs (<=2)
        for (int ks = 0; ks < 8; ++ks) {
            u32 a2[2][4];
            const u32 ci = (u32)(ks * 2 + lh);
#pragma unroll
            for (int sp = 0; sp < 2; ++sp) {
                int ri = rbase + sp * 16 + li;
                ldsm4(a2[sp], sb + SM_Q + (u32)ri * 256 + ((ci ^ (ri & 7)) << 4));
            }
            for (int jp = 0; jp < ph; ++jp) {
                int ri = c4 * 32 + jp * 16 + li;      // local K row
                u32 b4[4];
                ldsm4(b4, sb + SM_K + (u32)ri * 256 + ((ci ^ (ri & 7)) << 4));
#pragma unroll
                for (int sp = 0; sp < 2; ++sp) {
                    mma16816(D[hk * 8 + sp * 4 + 2 * jp],     a2[sp], b4[0], b4[2]);
                    mma16816(D[hk * 8 + sp * 4 + 2 * jp + 1], a2[sp], b4[1], b4[3]);
                }
            }
        }
    }

    // ---- Softmax: local max -> B1 ----
#pragma unroll
    for (int slot = 0; slot < 4; ++slot) {
        int sp = slot >> 1, hf = slot & 1;
        int row = rbase + sp * 16 + gq + hf * 8;
        int s = s0 + row;
        int nv = (s >= 31) ? (((s - 31) >> 4) + 1) : 0;
        float mloc = -1e30f;
#pragma unroll
        for (int hk = 0; hk < 2; ++hk)
#pragma unroll
            for (int j = 0; j < 4; ++j) {
                int c0 = hk * 128 + c4 * 32 + j * 8 + 2 * tq;
                float* dd = D[hk * 8 + sp * 4 + j];
                if (c0     < nv) mloc = fmaxf(mloc, dd[hf * 2]     * SCALE);
                if (c0 + 1 < nv) mloc = fmaxf(mloc, dd[hf * 2 + 1] * SCALE);
            }
        mloc = fmaxf(mloc, __shfl_xor_sync(0xffffffffu, mloc, 1));
        mloc = fmaxf(mloc, __shfl_xor_sync(0xffffffffu, mloc, 2));
        if (tq == 0) rmax[c4 * 64 + row] = mloc;
    }
    __syncthreads();                          // B1

    // ---- Softmax: exp + sum -> B2 ----
#pragma unroll
    for (int slot = 0; slot < 4; ++slot) {
        int sp = slot >> 1, hf = slot & 1;
        int row = rbase + sp * 16 + gq + hf * 8;
        int s = s0 + row;
        int nv = (s >= 31) ? (((s - 31) >> 4) + 1) : 0;
        float m = fmaxf(fmaxf(rmax[row], rmax[64 + row]),
                        fmaxf(rmax[128 + row], rmax[192 + row]));
        float sl = 0.f;
#pragma unroll
        for (int hk = 0; hk < 2; ++hk)
#pragma unroll
            for (int j = 0; j < 4; ++j) {
                int c0 = hk * 128 + c4 * 32 + j * 8 + 2 * tq;
                float* dd = D[hk * 8 + sp * 4 + j];
                float e0 = (c0     < nv) ? __expf(dd[hf * 2]     * SCALE - m) : 0.f;
                float e1 = (c0 + 1 < nv) ? __expf(dd[hf * 2 + 1] * SCALE - m) : 0.f;
                dd[hf * 2]     = e0;
                dd[hf * 2 + 1] = e1;
                sl += e0 + e1;
            }
        sl += __shfl_xor_sync(0xffffffffu, sl, 1);
        sl += __shfl_xor_sync(0xffffffffu, sl, 2);
        if (tq == 0) rsum[c4 * 64 + row] = sl;
    }
    __syncthreads();                          // B2: K reads done -> P may overlay

    // ---- Normalize + attn write (scalar: NBL odd!) + P -> smem fp16 ----
#pragma unroll
    for (int slot = 0; slot < 4; ++slot) {
        int sp = slot >> 1, hf = slot & 1;
        int row = rbase + sp * 16 + gq + hf * 8;
        float tot = rsum[row] + rsum[64 + row] + rsum[128 + row] + rsum[192 + row];
        float inv = 1.f / fmaxf(tot, 1e-20f);
        size_t arow = (((size_t)b * HQN + hq) * SEQ + s0 + row) * NBL;
#pragma unroll
        for (int hk = 0; hk < 2; ++hk)
#pragma unroll
            for (int j = 0; j < 4; ++j) {
                int c0 = hk * 128 + c4 * 32 + j * 8 + 2 * tq;
                float* dd = D[hk * 8 + sp * 4 + j];
                float p0 = dd[hf * 2]     * inv;
                float p1 = dd[hf * 2 + 1] * inv;
                if (write_attn) {
                    attn[arow + c0] = p0;             // c0 <= 254 always
                    if (c0 + 1 < NBL) attn[arow + c0 + 1] = p1;
                }
                u32 ch = (u32)((hk * 16 + c4 * 4 + j) ^ (row & 7));
                u32 off = (u32)row * 512 + (ch << 4) + tq * 4;
                *(u32*)(smc + SM_P + off) = pkhf(__float2half_rn(p0), __float2half_rn(p1));
            }
    }
    __syncthreads();                          // B3: P visible

    // ---- Phase C: 32-nb V chunks, double-buffered ----
    const int dbase = c4 * 32;
    float C[8][4];
#pragma unroll
    for (int i = 0; i < 8; ++i) { C[i][0] = C[i][1] = C[i][2] = C[i][3] = 0.f; }

    for (int kc = 0; kc < nch; ++kc) {
        if (kc + 1 < nch) { CP_WAIT(1); }     // pending ⊆ {V_kc, V_kc+1} -> drains V_kc
        else             { CP_WAIT(0); }      // LAST chunk: nothing younger -> full drain
        __syncthreads();
        const u32 sbV = sb + ((kc & 1) ? SM_V1 : SM_V0);
        const int kslo = kc * 2;
        const int kshi = min(kslo + 2, KSC);
        for (int ks = kslo; ks < kshi; ++ks) {
            u32 p2[2][4];
            const u32 ciP = (u32)(ks * 2 + lh);
#pragma unroll
            for (int sp = 0; sp < 2; ++sp) {
                int ri = rbase + sp * 16 + li;
                ldsm4(p2[sp], sb + SM_P + (u32)ri * 512 + ((ciP ^ (ri & 7)) << 4));
            }
            const u32 ciV = (u32)((ks - kslo) * 2 + lh);
#pragma unroll
            for (int dp = 0; dp < 2; ++dp) {
                int ri = dbase + dp * 16 + li;
                u32 b4[4];
                ldsm4(b4, sbV + (u32)ri * 80 + ciV * 16);
#pragma unroll
                for (int sp = 0; sp < 2; ++sp) {
                    mma16816(C[sp * 4 + 2 * dp],     p2[sp], b4[0], b4[2]);
                    mma16816(C[sp * 4 + 2 * dp + 1], p2[sp], b4[1], b4[3]);
                }
            }
        }
        __syncthreads();                      // reads of chunk kc done
        if (kc + 2 < nch) {
            const u32 dstb = sb + ((kc & 1) ? SM_V1 : SM_V0);
            for (int u = tid; u < 512; u += 256) {
                int dd = u >> 2, cc = u & 3;
                CP_A16(dstb + (u32)dd * 80 + (u32)cc * 16,
                       g_vt16 + bhoff + dd * 256 + (kc + 2) * 32 + cc * 8);
            }
            CP_COMMIT();
        }
    }

    // ---- Store out: (BS, S, HQ, D), float2 per fragment pair ----
#pragma unroll
    for (int slot = 0; slot < 4; ++slot) {
        int sp = slot >> 1, hf = slot & 1;
        int row = rbase + sp * 16 + gq + hf * 8;
        float* op = out + ((size_t)(b * SEQ + s0 + row) * HQN + hq) * DIM + dbase;
#pragma unroll
        for (int dt = 0; dt < 4; ++dt) {
            *(float2*)(op + dt * 8 + 2 * tq) =
                make_float2(C[sp * 4 + dt][hf * 2], C[sp * 4 + dt][hf * 2 + 1]);
        }
    }
}

// ---------------------------------------------------------------------------
extern "C" void kernel_launch(void* const* d_in, const int* in_sizes, int n_in,
                              void* d_out, int out_size)
{
    const float* q   = (const float*)d_in[0];
    const float* k   = (const float*)d_in[1];
    const float* v   = (const float*)d_in[2];
    // d_in[3] = cu_seqlens_k (fixed [0,S,2S]) — unused
    const float* wk  = (const float*)d_in[4];
    const float* wv  = (const float*)d_in[5];
    const float* pek = (const float*)d_in[6];
    const float* pev = (const float*)d_in[7];

    float* out  = (float*)d_out;
    float* attn = out + OUT_ELEMS;
    int write_attn = ((size_t)out_size >= OUT_ELEMS + ATTN_ELEMS) ? 1 : 0;

    cudaFuncSetAttribute(compress_mma,
                         cudaFuncAttributeMaxDynamicSharedMemorySize, CM_SMEM);
    cudaFuncSetAttribute(attn_kernel,
                         cudaFuncAttributeMaxDynamicSharedMemorySize, ATT_SMEM);

    wconv_kernel<<<dim3(512, 2), 256>>>(wk, wv);
    compress_mma<<<dim3(16, 4, 2), 256, CM_SMEM>>>(k, v, pek, pev);
    attn_kernel<<<dim3(64, 16, 4), 256, ATT_SMEM>>>(q, out, attn, write_attn);
}

// round 15
// speedup vs baseline: 4.7768x; 1.0111x over previous
#include <cuda_runtime.h>
#include <cuda_fp16.h>

// Problem constants (fixed by reference setup)
#define BSZ     2
#define SEQ     4096
#define HQN     32
#define HKV     2
#define DIM     128
#define NBL     255
#define GRP     16
#define SCALE   0.08838834764831845f   // 1/sqrt(128)

#define OUT_ELEMS  ((size_t)BSZ*SEQ*HQN*DIM)            // 33,554,432
#define ATTN_ELEMS ((size_t)BSZ*HQN*SEQ*NBL)            // 66,846,720

typedef unsigned long long ull;
typedef unsigned int       u32;

// Compressed K/V in fp16. nb padded to 256; index 255 stays zero
// (device globals are zero-initialized; row 255 is never written).
// K: [bh][nb(256)][d(128)]   V (pre-transposed): [bh][d(128)][nb(256)]
__device__ __half g_k16 [4*256*128];
__device__ __half g_vt16[4*128*256];
// W pre-converted to fp16: [t][e(4096)][d(128)]
__device__ __half g_w16 [2*4096*128];

// ---- warp-MMA helpers (sm_80-class, valid on non-'a' target) --------------
__device__ __forceinline__ u32 smem_u32(const void* p) {
    u32 a; asm("{ .reg .u64 t; cvta.to.shared.u64 t, %1; cvt.u32.u64 %0, t; }"
               : "=r"(a) : "l"(p));
    return a;
}
__device__ __forceinline__ void ldsm4(u32* r, u32 addr) {
    asm volatile("ldmatrix.sync.aligned.m8n8.x4.shared.b16 {%0,%1,%2,%3}, [%4];"
        : "=r"(r[0]), "=r"(r[1]), "=r"(r[2]), "=r"(r[3]) : "r"(addr));
}
__device__ __forceinline__ void ldsm4t(u32* r, u32 addr) {
    asm volatile("ldmatrix.sync.aligned.m8n8.x4.trans.shared.b16 {%0,%1,%2,%3}, [%4];"
        : "=r"(r[0]), "=r"(r[1]), "=r"(r[2]), "=r"(r[3]) : "r"(addr));
}
__device__ __forceinline__ void mma16816(float* d, const u32* a, u32 b0, u32 b1) {
    asm volatile("mma.sync.aligned.m16n8k16.row.col.f32.f16.f16.f32 "
        "{%0,%1,%2,%3},{%4,%5,%6,%7},{%8,%9},{%0,%1,%2,%3};"
        : "+f"(d[0]), "+f"(d[1]), "+f"(d[2]), "+f"(d[3])
        : "r"(a[0]), "r"(a[1]), "r"(a[2]), "r"(a[3]), "r"(b0), "r"(b1));
}
__device__ __forceinline__ u32 pkhf(__half a, __half b) {
    __half2 t(a, b);                        // .x at low halfword
    return *(u32*)&t;
}
#define CP_A16(dst, src) \
    asm volatile("cp.async.cg.shared.global [%0], [%1], 16;" \
                 :: "r"(dst), "l"(src) : "memory")
#define CP_COMMIT()  asm volatile("cp.async.commit_group;" ::: "memory")
#define CP_WAIT(N)   asm volatile("cp.async.wait_group %0;" :: "n"(N) : "memory")

// ---------------------------------------------------------------------------
// W fp32 -> fp16 conversion. grid (512, 2), block 256. 131072 float4 per t.
// ---------------------------------------------------------------------------
__global__ __launch_bounds__(256)
void wconv_kernel(const float* __restrict__ wk, const float* __restrict__ wv)
{
    const float* src = blockIdx.y ? wv : wk;
    __half* dst = g_w16 + (size_t)blockIdx.y * 524288;
    int i = blockIdx.x * 256 + threadIdx.x;
    float4 v = ((const float4*)src)[i];
    uint2 o;
    o.x = pkhf(__float2half_rn(v.x), __float2half_rn(v.y));
    o.y = pkhf(__float2half_rn(v.z), __float2half_rn(v.w));
    ((uint2*)dst)[i] = o;
}

// ---------------------------------------------------------------------------
// Compression via HMMA. grid (16 nbg, 4 bh, 2 t), block 256 (8 warps).
// Per CTA: C[16 nb, 128 d] = A[16, 4096]·W[4096, 128], K streamed as 32
// blk-chunks of 128 e-values. A[nb, blk*128+dd] = x[(nb0+nb)*16+blk][dd] +
// pe[blk][dd], staged fp32-add + fp16-convert into a 4KB swizzled buffer.
// W chunks (32KB fp16, k-major [e][d]) stream via cp.async double-buffer
// from g_w16; B fragments via ldmatrix.x4.trans. Warp w owns d-cols w*16.
// cp.async LEDGER: prologue commits w0, w1; every loop iter commits exactly
// ONE group (empty when blk+2 >= 32) after the compute-done sync, then
// CP_WAIT(1) drains w_{blk+1}. Buffer reuse is barrier-protected.
// SMEM: A 2x4KB @0 | W 2x32KB @8192   total 73,728 B   (2 CTAs/SM)
// ---------------------------------------------------------------------------
#define CM_A_OFF 0
#define CM_W_OFF 8192
#define CM_SMEM  73728

__global__ __launch_bounds__(256, 2)
void compress_mma(const float* __restrict__ kin, const float* __restrict__ vin,
                  const float* __restrict__ pek, const float* __restrict__ pev)
{
    extern __shared__ char smc[];
    const u32 sb = smem_u32(smc);

    const int nbg = blockIdx.x;              // 0..15
    const int bh  = blockIdx.y;              // b*2+h
    const int b   = bh >> 1, h = bh & 1;
    const int t   = blockIdx.z;              // 0=k, 1=v

    const float*  x    = t ? vin : kin;
    const float*  pe   = t ? pev : pek;
    const __half* w16g = g_w16 + (size_t)t * 524288;

    const int tid  = threadIdx.x;
    const int w    = tid >> 5;
    const int lane = tid & 31;
    const int li = lane & 15, lh = lane >> 4;
    const int gq = lane >> 2, tq = lane & 3;
    const int dw = w * 16;                   // warp's d-range [dw, dw+16)
    const int nb0 = nbg * 16;

    // -- A stage: chunk blk -> Abuf[buf] (16 rows x 128 e fp16, swizzled) --
    auto a_stage = [&](int blk, int buf) {
        const int row = tid >> 4;            // 0..15
        const int c2  = tid & 15;
        const int nb  = nb0 + row;
        const float* xrowp = x + ((size_t)(b * SEQ + nb * 16 + blk) * HKV + h) * DIM;
        const float* pep   = pe + blk * 128;
        char* abase = smc + CM_A_OFF + buf * 4096;
#pragma unroll
        for (int j = 0; j < 4; ++j) {
            int e2 = c2 + 16 * j;            // u32 index; dd = e2*2
            float2 xv = make_float2(0.f, 0.f);
            if (nb < NBL) xv = *(const float2*)(xrowp + e2 * 2);
            float2 pv = *(const float2*)(pep + e2 * 2);
            u32 off = (u32)row * 256 + ((((u32)e2 >> 2) ^ (row & 7)) << 4) + (e2 & 3) * 4;
            *(u32*)(abase + off) = pkhf(__float2half_rn(xv.x + pv.x),
                                        __float2half_rn(xv.y + pv.y));
        }
    };
    // -- W stage: chunk blk -> Wbuf[buf] via cp.async (128 e x 128 d fp16) --
    auto w_stage = [&](int blk, int buf) {
        const __half* wp = w16g + (size_t)blk * 16384;
        for (int u = tid; u < 2048; u += 256) {
            int e = u >> 4, cc = u & 15;
            u32 dst = sb + CM_W_OFF + buf * 32768
                    + (u32)e * 256 + (u32)((cc ^ (e & 7)) << 4);
            CP_A16(dst, wp + e * 128 + cc * 8);
        }
    };

    float acc[8];
#pragma unroll
    for (int i = 0; i < 8; ++i) acc[i] = 0.f;

    // prologue: w0, w1 committed; A0 staged; drain w0
    w_stage(0, 0); CP_COMMIT();
    w_stage(1, 1); CP_COMMIT();
    a_stage(0, 0);
    CP_WAIT(1);
    __syncthreads();

    for (int blk = 0; blk < 32; ++blk) {
        const int buf = blk & 1;
        // compute chunk blk: 8 k16 steps
#pragma unroll
        for (int ks = 0; ks < 8; ++ks) {
            u32 a4[4];
            ldsm4(a4, sb + CM_A_OFF + buf * 4096
                      + (u32)li * 256 + ((((u32)(ks * 2 + lh)) ^ (li & 7)) << 4));
            u32 b4[4];
            int e = ks * 16 + ((lane >> 3) & 1) * 8 + (lane & 7);
            u32 cd = (u32)((dw >> 3) + (lane >> 4));
            ldsm4t(b4, sb + CM_W_OFF + buf * 32768
                       + (u32)e * 256 + ((cd ^ (e & 7)) << 4));
            mma16816(acc,     a4, b4[0], b4[1]);   // n-tile dw..dw+8
            mma16816(acc + 4, a4, b4[2], b4[3]);   // n-tile dw+8..dw+16
        }
        __syncthreads();                      // all reads of buf done
        if (blk + 2 < 32) w_stage(blk + 2, buf);
        CP_COMMIT();                          // ALWAYS one group per iter
        if (blk + 1 < 32) a_stage(blk + 1, (blk + 1) & 1);
        CP_WAIT(1);                           // drains w_{blk+1}
        __syncthreads();
    }

    // -- Epilogue: C frags -> global fp16 outputs --
    const int nbr0 = nb0 + gq, nbr1 = nb0 + gq + 8;
    if (t == 0) {
        __half* base = g_k16 + (size_t)(bh * 256) * 128;
        if (nbr0 < NBL) {
            __half* p = base + (size_t)nbr0 * 128 + dw + 2 * tq;
            *(u32*)p       = pkhf(__float2half_rn(acc[0]), __float2half_rn(acc[1]));
            *(u32*)(p + 8) = pkhf(__float2half_rn(acc[4]), __float2half_rn(acc[5]));
        }
        if (nbr1 < NBL) {
            __half* p = base + (size_t)nbr1 * 128 + dw + 2 * tq;
            *(u32*)p       = pkhf(__float2half_rn(acc[2]), __float2half_rn(acc[3]));
            *(u32*)(p + 8) = pkhf(__float2half_rn(acc[6]), __float2half_rn(acc[7]));
        }
    } else {
        __half* vb = g_vt16 + (size_t)(bh * 128) * 256;
        const int d0 = dw + 2 * tq;
        if (nbr0 < NBL) {
            vb[(size_t)d0 * 256 + nbr0]       = __float2half_rn(acc[0]);
            vb[(size_t)(d0 + 1) * 256 + nbr0] = __float2half_rn(acc[1]);
            vb[(size_t)(d0 + 8) * 256 + nbr0] = __float2half_rn(acc[4]);
            vb[(size_t)(d0 + 9) * 256 + nbr0] = __float2half_rn(acc[5]);
        }
        if (nbr1 < NBL) {
            vb[(size_t)d0 * 256 + nbr1]       = __float2half_rn(acc[2]);
            vb[(size_t)(d0 + 1) * 256 + nbr1] = __float2half_rn(acc[3]);
            vb[(size_t)(d0 + 8) * 256 + nbr1] = __float2half_rn(acc[6]);
            vb[(size_t)(d0 + 9) * 256 + nbr1] = __float2half_rn(acc[7]);
        }
    }
}

// ---------------------------------------------------------------------------
// Attention kernel — fp16 warp MMA, 3 CTAs/SM. VERBATIM from R12 (passing).
// ---------------------------------------------------------------------------
#define SM_RMAX  0
#define SM_RSUM  1024
#define SM_Q     2048
#define SM_K     18432
#define SM_P     SM_K
#define SM_V0    51200
#define SM_V1    61440
#define ATT_SMEM 71680

__global__ __launch_bounds__(256, 3)
void attn_kernel(const float* __restrict__ q, float* __restrict__ out,
                 float* __restrict__ attn, int write_attn)
{
    extern __shared__ char smc[];
    const u32 sb = smem_u32(smc);
    float* rmax = (float*)(smc + SM_RMAX);   // [4 c4][64 rows]
    float* rsum = (float*)(smc + SM_RSUM);

    const int st = 63 - blockIdx.x;          // heavy-first
    const int g  = blockIdx.y;
    const int bh = blockIdx.z;
    const int b  = bh >> 1, h = bh & 1;
    const int hq = h * GRP + g;
    const int s0 = st * 64;
    const int tid  = threadIdx.x;
    const int w    = tid >> 5;
    const int lane = tid & 31;
    const int r2 = w >> 2, c4 = w & 3;
    const int gq = lane >> 2, tq = lane & 3;
    const int li = lane & 15, lh = lane >> 4;

    const int NVC = st * 4 + 3;              // max valid col count (odd)
    const int KR  = (NVC + 15) & ~15;        // total valid K rows (<=256)
    const int KR0 = min(KR, 128);
    const int KR1 = KR - KR0;                // >0 iff st>=32
    const int rbase = r2 * 32;
    const size_t bhoff = (size_t)bh * 32768;

    const int KSC = KR >> 4;                 // k16 steps for phase C (<=16)
    const int nch = (KSC + 1) >> 1;          // 32-nb V chunks (<=8)

    // ---- group 1: K half0 ----
    for (int u = tid; u < KR0 * 16; u += 256) {
        int nb = u >> 4, c = u & 15;
        u32 dst = sb + SM_K + (u32)nb * 256 + (u32)((c ^ (nb & 7)) << 4);
        CP_A16(dst, g_k16 + bhoff + nb * 128 + c * 8);
    }
    CP_COMMIT();
    // ---- group 2: V chunk 0 ----
    for (int u = tid; u < 512; u += 256) {
        int dd = u >> 2, cc = u & 3;
        CP_A16(sb + SM_V0 + (u32)dd * 80 + (u32)cc * 16,
               g_vt16 + bhoff + dd * 256 + cc * 8);
    }
    CP_COMMIT();
    // ---- group 3: V chunk 1 (EMPTY group when nch==1 — keeps the count) ----
    if (nch > 1) {
        for (int u = tid; u < 512; u += 256) {
            int dd = u >> 2, cc = u & 3;
            CP_A16(sb + SM_V1 + (u32)dd * 80 + (u32)cc * 16,
                   g_vt16 + bhoff + dd * 256 + 32 + cc * 8);
        }
    }
    CP_COMMIT();                              // ALWAYS the 3rd group
    // ---- Stage Q (f32 -> fp16), swizzled 256B rows ----
    for (int u = tid; u < 4096; u += 256) {
        int r = u >> 6, k2 = u & 63;
        float2 qv = *(const float2*)(q + ((size_t)((b * SEQ + s0 + r) * HQN + hq)) * DIM + k2 * 2);
        u32 off = (u32)r * 256 + (((((u32)k2) >> 2) ^ (r & 7)) << 4) + (k2 & 3) * 4;
        *(u32*)(smc + SM_Q + off) = pkhf(__float2half_rn(qv.x), __float2half_rn(qv.y));
    }
    CP_WAIT(2);                               // drains K half0 (3 groups committed)
    __syncthreads();

    // ---- Phase A: D[2 half][8 tile][4]; warp covers 32 cols per half ----
    float D[16][4];
#pragma unroll
    for (int i = 0; i < 16; ++i) { D[i][0] = D[i][1] = D[i][2] = D[i][3] = 0.f; }

#pragma unroll
    for (int hk = 0; hk < 2; ++hk) {
        if (hk == 1) {
            if (KR1 <= 0) break;
            __syncthreads();                  // all reads of K half0 done
            for (int u = tid; u < KR1 * 16; u += 256) {
                int nb = u >> 4, c = u & 15;
                u32 dst = sb + SM_K + (u32)nb * 256 + (u32)((c ^ (nb & 7)) << 4);
                CP_A16(dst, g_k16 + bhoff + (128 + nb) * 128 + c * 8);
            }
            CP_COMMIT();
            CP_WAIT(0);                       // drains V0/V1 too (issued early)
            __syncthreads();
        }
        const int cw = hk * 128 + c4 * 32;    // warp's first score col
        int jt = (NVC - cw + 7) >> 3;
        jt = (jt < 0) ? 0 : ((jt > 4) ? 4 : jt);
        const int ph = (jt + 1) >> 1;         // 16-col pairs (<=2)
        for (int ks = 0; ks < 8; ++ks) {
            u32 a2[2][4];
            const u32 ci = (u32)(ks * 2 + lh);
#pragma unroll
            for (int sp = 0; sp < 2; ++sp) {
                int ri = rbase + sp * 16 + li;
                ldsm4(a2[sp], sb + SM_Q + (u32)ri * 256 + ((ci ^ (ri & 7)) << 4));
            }
            for (int jp = 0; jp < ph; ++jp) {
                int ri = c4 * 32 + jp * 16 + li;      // local K row
                u32 b4[4];
                ldsm4(b4, sb + SM_K + (u32)ri * 256 + ((ci ^ (ri & 7)) << 4));
#pragma unroll
                for (int sp = 0; sp < 2; ++sp) {
                    mma16816(D[hk * 8 + sp * 4 + 2 * jp],     a2[sp], b4[0], b4[2]);
                    mma16816(D[hk * 8 + sp * 4 + 2 * jp + 1], a2[sp], b4[1], b4[3]);
                }
            }
        }
    }

    // ---- Softmax: local max -> B1 ----
#pragma unroll
    for (int slot = 0; slot < 4; ++slot) {
        int sp = slot >> 1, hf = slot & 1;
        int row = rbase + sp * 16 + gq + hf * 8;
        int s = s0 + row;
        int nv = (s >= 31) ? (((s - 31) >> 4) + 1) : 0;
        float mloc = -1e30f;
#pragma unroll
        for (int hk = 0; hk < 2; ++hk)
#pragma unroll
            for (int j = 0; j < 4; ++j) {
                int c0 = hk * 128 + c4 * 32 + j * 8 + 2 * tq;
                float* dd = D[hk * 8 + sp * 4 + j];
                if (c0     < nv) mloc = fmaxf(mloc, dd[hf * 2]     * SCALE);
                if (c0 + 1 < nv) mloc = fmaxf(mloc, dd[hf * 2 + 1] * SCALE);
            }
        mloc = fmaxf(mloc, __shfl_xor_sync(0xffffffffu, mloc, 1));
        mloc = fmaxf(mloc, __shfl_xor_sync(0xffffffffu, mloc, 2));
        if (tq == 0) rmax[c4 * 64 + row] = mloc;
    }
    __syncthreads();                          // B1

    // ---- Softmax: exp + sum -> B2 ----
#pragma unroll
    for (int slot = 0; slot < 4; ++slot) {
        int sp = slot >> 1, hf = slot & 1;
        int row = rbase + sp * 16 + gq + hf * 8;
        int s = s0 + row;
        int nv = (s >= 31) ? (((s - 31) >> 4) + 1) : 0;
        float m = fmaxf(fmaxf(rmax[row], rmax[64 + row]),
                        fmaxf(rmax[128 + row], rmax[192 + row]));
        float sl = 0.f;
#pragma unroll
        for (int hk = 0; hk < 2; ++hk)
#pragma unroll
            for (int j = 0; j < 4; ++j) {
                int c0 = hk * 128 + c4 * 32 + j * 8 + 2 * tq;
                float* dd = D[hk * 8 + sp * 4 + j];
                float e0 = (c0     < nv) ? __expf(dd[hf * 2]     * SCALE - m) : 0.f;
                float e1 = (c0 + 1 < nv) ? __expf(dd[hf * 2 + 1] * SCALE - m) : 0.f;
                dd[hf * 2]     = e0;
                dd[hf * 2 + 1] = e1;
                sl += e0 + e1;
            }
        sl += __shfl_xor_sync(0xffffffffu, sl, 1);
        sl += __shfl_xor_sync(0xffffffffu, sl, 2);
        if (tq == 0) rsum[c4 * 64 + row] = sl;
    }
    __syncthreads();                          // B2: K reads done -> P may overlay

    // ---- Normalize + attn write (scalar: NBL odd!) + P -> smem fp16 ----
#pragma unroll
    for (int slot = 0; slot < 4; ++slot) {
        int sp = slot >> 1, hf = slot & 1;
        int row = rbase + sp * 16 + gq + hf * 8;
        float tot = rsum[row] + rsum[64 + row] + rsum[128 + row] + rsum[192 + row];
        float inv = 1.f / fmaxf(tot, 1e-20f);
        size_t arow = (((size_t)b * HQN + hq) * SEQ + s0 + row) * NBL;
#pragma unroll
        for (int hk = 0; hk < 2; ++hk)
#pragma unroll
            for (int j = 0; j < 4; ++j) {
                int c0 = hk * 128 + c4 * 32 + j * 8 + 2 * tq;
                float* dd = D[hk * 8 + sp * 4 + j];
                float p0 = dd[hf * 2]     * inv;
                float p1 = dd[hf * 2 + 1] * inv;
                if (write_attn) {
                    attn[arow + c0] = p0;             // c0 <= 254 always
                    if (c0 + 1 < NBL) attn[arow + c0 + 1] = p1;
                }
                u32 ch = (u32)((hk * 16 + c4 * 4 + j) ^ (row & 7));
                u32 off = (u32)row * 512 + (ch << 4) + tq * 4;
                *(u32*)(smc + SM_P + off) = pkhf(__float2half_rn(p0), __float2half_rn(p1));
            }
    }
    __syncthreads();                          // B3: P visible

    // ---- Phase C: 32-nb V chunks, double-buffered ----
    const int dbase = c4 * 32;
    float C[8][4];
#pragma unroll
    for (int i = 0; i < 8; ++i) { C[i][0] = C[i][1] = C[i][2] = C[i][3] = 0.f; }

    for (int kc = 0; kc < nch; ++kc) {
        if (kc + 1 < nch) { CP_WAIT(1); }     // pending ⊆ {V_kc, V_kc+1} -> drains V_kc
        else             { CP_WAIT(0); }      // LAST chunk: nothing younger -> full drain
        __syncthreads();
        const u32 sbV = sb + ((kc & 1) ? SM_V1 : SM_V0);
        const int kslo = kc * 2;
        const int kshi = min(kslo + 2, KSC);
        for (int ks = kslo; ks < kshi; ++ks) {
            u32 p2[2][4];
            const u32 ciP = (u32)(ks * 2 + lh);
#pragma unroll
            for (int sp = 0; sp < 2; ++sp) {
                int ri = rbase + sp * 16 + li;
                ldsm4(p2[sp], sb + SM_P + (u32)ri * 512 + ((ciP ^ (ri & 7)) << 4));
            }
            const u32 ciV = (u32)((ks - kslo) * 2 + lh);
#pragma unroll
            for (int dp = 0; dp < 2; ++dp) {
                int ri = dbase + dp * 16 + li;
                u32 b4[4];
                ldsm4(b4, sbV + (u32)ri * 80 + ciV * 16);
#pragma unroll
                for (int sp = 0; sp < 2; ++sp) {
                    mma16816(C[sp * 4 + 2 * dp],     p2[sp], b4[0], b4[2]);
                    mma16816(C[sp * 4 + 2 * dp + 1], p2[sp], b4[1], b4[3]);
                }
            }
        }
        __syncthreads();                      // reads of chunk kc done
        if (kc + 2 < nch) {
            const u32 dstb = sb + ((kc & 1) ? SM_V1 : SM_V0);
            for (int u = tid; u < 512; u += 256) {
                int dd = u >> 2, cc = u & 3;
                CP_A16(dstb + (u32)dd * 80 + (u32)cc * 16,
                       g_vt16 + bhoff + dd * 256 + (kc + 2) * 32 + cc * 8);
            }
            CP_COMMIT();
        }
    }

    // ---- Store out: (BS, S, HQ, D), float2 per fragment pair ----
#pragma unroll
    for (int slot = 0; slot < 4; ++slot) {
        int sp = slot >> 1, hf = slot & 1;
        int row = rbase + sp * 16 + gq + hf * 8;
        float* op = out + ((size_t)(b * SEQ + s0 + row) * HQN + hq) * DIM + dbase;
#pragma unroll
        for (int dt = 0; dt < 4; ++dt) {
            *(float2*)(op + dt * 8 + 2 * tq) =
                make_float2(C[sp * 4 + dt][hf * 2], C[sp * 4 + dt][hf * 2 + 1]);
        }
    }
}

// ---------------------------------------------------------------------------
extern "C" void kernel_launch(void* const* d_in, const int* in_sizes, int n_in,
                              void* d_out, int out_size)
{
    const float* q   = (const float*)d_in[0];
    const float* k   = (const float*)d_in[1];
    const float* v   = (const float*)d_in[2];
    // d_in[3] = cu_seqlens_k (fixed [0,S,2S]) — unused
    const float* wk  = (const float*)d_in[4];
    const float* wv  = (const float*)d_in[5];
    const float* pek = (const float*)d_in[6];
    const float* pev = (const float*)d_in[7];

    float* out  = (float*)d_out;
    float* attn = out + OUT_ELEMS;
    int write_attn = ((size_t)out_size >= OUT_ELEMS + ATTN_ELEMS) ? 1 : 0;

    cudaFuncSetAttribute(compress_mma,
                         cudaFuncAttributeMaxDynamicSharedMemorySize, CM_SMEM);
    cudaFuncSetAttribute(attn_kernel,
                         cudaFuncAttributeMaxDynamicSharedMemorySize, ATT_SMEM);

    wconv_kernel<<<dim3(512, 2), 256>>>(wk, wv);
    compress_mma<<<dim3(16, 4, 2), 256, CM_SMEM>>>(k, v, pek, pev);
    attn_kernel<<<dim3(64, 16, 4), 256, ATT_SMEM>>>(q, out, attn, write_attn);
}